// round 13
// baseline (speedup 1.0000x reference)
#include <cuda_runtime.h>
#include <cuda_fp16.h>
#include <math.h>
#include <stdint.h>

// ---------------- problem constants ----------------
#define BATCH   2
#define SEQLEN  512
#define DMODEL  1024
#define DINNER  2048
#define NHEADS  32
#define HEADDIM 64
#define DSTATE  128
#define DCONV   4
#define DPROJ   4384   // 2*DINNER + 2*DSTATE + NHEADS
#define NPAD    4608   // DPROJ padded to multiple of 256
#define CONVD   2304   // DINNER + 2*DSTATE
#define MROWS   (BATCH*SEQLEN)   // 1024
#define DT_OFF  (DINNER + CONVD) // 4352
#define SEGLEN  256              // sequence segment length (2 segments)

// ---------------- scratch (static device memory) ----------------
__device__ float g_zx [MROWS * DPROJ];      // in_proj output  (1024 x 4384)
__device__ float g_xbc[MROWS * CONVD];      // conv+silu output
__device__ float g_yp [4][MROWS * DINNER];  // scan partial outputs (4 n-chunks)
__device__ float g_sstate[64 * HEADDIM * DSTATE];  // seg0 final states per bh
__device__ float g_cd[64 * SEGLEN];         // cumulative decay in seg1 per bh

__device__ __half g_uh [MROWS * DMODEL];
__device__ __half g_ul [MROWS * DMODEL];
__device__ __half g_wih[NPAD  * DMODEL];
__device__ __half g_ynh[MROWS * DINNER];
__device__ __half g_ynl[MROWS * DINNER];
__device__ __half g_woh[DMODEL * DINNER];

// =====================================================================
// helpers
// =====================================================================
__device__ __forceinline__ uint32_t smem_u32(const void* p) {
    uint32_t a;
    asm("{ .reg .u64 t; cvta.to.shared.u64 t, %1; cvt.u32.u64 %0, t; }"
        : "=r"(a) : "l"(p));
    return a;
}

__device__ __forceinline__ void cpa16(uint32_t dst, const void* src) {
    asm volatile("cp.async.cg.shared.global [%0], [%1], 16;"
                 :: "r"(dst), "l"(src) : "memory");
}
#define CP_COMMIT() asm volatile("cp.async.commit_group;" ::: "memory")

__device__ __forceinline__ void ldsm_x4(uint32_t addr, uint32_t& r0, uint32_t& r1,
                                        uint32_t& r2, uint32_t& r3) {
    asm volatile("ldmatrix.sync.aligned.m8n8.x4.shared.b16 {%0,%1,%2,%3}, [%4];"
                 : "=r"(r0), "=r"(r1), "=r"(r2), "=r"(r3) : "r"(addr));
}

__device__ __forceinline__ void mma_f16(float* c, const uint32_t* a,
                                        uint32_t b0, uint32_t b1) {
    asm volatile(
        "mma.sync.aligned.m16n8k16.row.col.f32.f16.f16.f32 "
        "{%0,%1,%2,%3}, {%4,%5,%6,%7}, {%8,%9}, {%0,%1,%2,%3};"
        : "+f"(c[0]), "+f"(c[1]), "+f"(c[2]), "+f"(c[3])
        : "r"(a[0]), "r"(a[1]), "r"(a[2]), "r"(a[3]), "r"(b0), "r"(b1));
}

__device__ __forceinline__ uint32_t pack_h2(float a, float b) {
    __half2 h = __floats2half2_rn(a, b);
    return *reinterpret_cast<uint32_t*>(&h);
}

#define F32X2_MUL(d, a, b) \
    asm("mul.rn.f32x2 %0, %1, %2;" : "=l"(d) : "l"(a), "l"(b))
#define F32X2_FMA(d, a, b) \
    asm("fma.rn.f32x2 %0, %0, %1, %2;" : "+l"(d) : "l"(a), "l"(b))
#define F32X2_FMA3(d, a, b) \
    asm("fma.rn.f32x2 %0, %1, %2, %0;" : "+l"(d) : "l"(a), "l"(b))
#define F32X2_BCAST(d, f) \
    asm("mov.b64 %0, {%1, %1};" : "=l"(d) : "f"(f))
#define F32X2_UNPACK(lo, hi, v) \
    asm("mov.b64 {%0, %1}, %2;" : "=f"(lo), "=f"(hi) : "l"(v))

// =====================================================================
// merged, vectorized fp32 -> fp16 conversions (u hi/lo, W_in hi, W_out hi)
// =====================================================================
#define CVT_N0 (MROWS * DMODEL)
#define CVT_N1 (NPAD * DMODEL)
#define CVT_N2 (DMODEL * DINNER)
#define CVT_TOT (CVT_N0 + CVT_N1 + CVT_N2)

__global__ __launch_bounds__(256) void convert_all(
    const float* __restrict__ u, const float* __restrict__ W_in,
    const float* __restrict__ W_out)
{
    int i = (blockIdx.x * 256 + threadIdx.x) * 4;
    if (i < CVT_N0) {
        float4 v = *reinterpret_cast<const float4*>(&u[i]);
        float hx = __half2float(__float2half_rn(v.x));
        float hy = __half2float(__float2half_rn(v.y));
        float hz = __half2float(__float2half_rn(v.z));
        float hw = __half2float(__float2half_rn(v.w));
        *reinterpret_cast<uint2*>(&g_uh[i]) =
            make_uint2(pack_h2(v.x, v.y), pack_h2(v.z, v.w));
        *reinterpret_cast<uint2*>(&g_ul[i]) =
            make_uint2(pack_h2(v.x - hx, v.y - hy), pack_h2(v.z - hz, v.w - hw));
    } else if (i < CVT_N0 + CVT_N1) {
        int j = i - CVT_N0;
        float4 v = make_float4(0.f, 0.f, 0.f, 0.f);
        if (j < DPROJ * DMODEL)
            v = *reinterpret_cast<const float4*>(&W_in[j]);
        *reinterpret_cast<uint2*>(&g_wih[j]) =
            make_uint2(pack_h2(v.x, v.y), pack_h2(v.z, v.w));
    } else if (i < CVT_TOT) {
        int j = i - CVT_N0 - CVT_N1;
        float4 v = *reinterpret_cast<const float4*>(&W_out[j]);
        *reinterpret_cast<uint2*>(&g_woh[j]) =
            make_uint2(pack_h2(v.x, v.y), pack_h2(v.z, v.w));
    }
}

// =====================================================================
// fp16 2-term split GEMM (NT) -- unchanged R8/R12 proven config
// =====================================================================
#define GS_ROWB 80
#define GS_STGB (512*GS_ROWB)
#define GS_SMEM (3*GS_STGB)
#define GS_AL_OFF (128*GS_ROWB)
#define GS_BH_OFF (256*GS_ROWB)

__global__ __launch_bounds__(256) void gemm_f16_2t(
    const __half* __restrict__ Ah, const __half* __restrict__ Al,
    const __half* __restrict__ Bh,
    float* __restrict__ C, int M, int N, int K, int accum)
{
    extern __shared__ char smem[];
    const uint32_t sbase = smem_u32(smem);
    const int tid = threadIdx.x;
    const int lane = tid & 31;
    const int warp = tid >> 5;
    const int wm = (warp >> 2) * 64;
    const int wn = (warp & 3) * 64;

    const int m0 = blockIdx.y * 128;
    const int n0 = blockIdx.x * 256;
    const int kslice = K / gridDim.z;
    const int kbeg = blockIdx.z * kslice;
    const int T = kslice / 32;

    float acc[4][8][4];
#pragma unroll
    for (int i = 0; i < 4; i++)
#pragma unroll
        for (int j = 0; j < 8; j++)
#pragma unroll
            for (int q = 0; q < 4; q++) acc[i][j][q] = 0.f;

    const __half* ptr0 = (tid < 128)
        ? Ah + (size_t)(m0 + tid) * K + kbeg
        : Al + (size_t)(m0 + tid - 128) * K + kbeg;
    const __half* ptr1 = Bh + (size_t)(n0 + tid) * K + kbeg;
    const uint32_t srow0 = sbase + tid * GS_ROWB;
    const uint32_t srow1 = sbase + (tid + 256) * GS_ROWB;

#define FILL_STAGE(STG, KOFF)                                                  \
    {                                                                          \
        uint32_t s0 = srow0 + (STG) * GS_STGB;                                 \
        uint32_t s1 = srow1 + (STG) * GS_STGB;                                 \
        _Pragma("unroll")                                                      \
        for (int sg = 0; sg < 4; sg++) {                                       \
            cpa16(s0 + sg * 16, ptr0 + (KOFF) + sg * 8);                       \
            cpa16(s1 + sg * 16, ptr1 + (KOFF) + sg * 8);                       \
        }                                                                      \
    }

    const uint32_t a_off = (uint32_t)((wm + (lane & 15)) * GS_ROWB + (lane >> 4) * 16);
    const uint32_t b_row = (uint32_t)(wn + ((lane >> 4) << 3) + (lane & 7));
    const uint32_t b_off = GS_BH_OFF + b_row * GS_ROWB + (((lane >> 3) & 1) << 4);

    FILL_STAGE(0, 0);
    CP_COMMIT();
    FILL_STAGE(1, 32);
    CP_COMMIT();

    for (int t = 0; t < T; t++) {
        asm volatile("cp.async.wait_group 1;" ::: "memory");
        __syncthreads();
        if (t + 2 < T) {
            int stg = (t + 2) % 3;
            FILL_STAGE(stg, (t + 2) * 32);
            CP_COMMIT();
        }

        const uint32_t sb = sbase + (t % 3) * GS_STGB;
#pragma unroll
        for (int ks = 0; ks < 2; ks++) {
            const uint32_t kb = ks * 32;
            uint32_t ah[4][4], al[4][4], bh[4][4];
#pragma unroll
            for (int mi = 0; mi < 4; mi++) {
                uint32_t ad = sb + a_off + mi * 16 * GS_ROWB + kb;
                ldsm_x4(ad, ah[mi][0], ah[mi][1], ah[mi][2], ah[mi][3]);
                ldsm_x4(ad + GS_AL_OFF, al[mi][0], al[mi][1], al[mi][2], al[mi][3]);
            }
#pragma unroll
            for (int bi = 0; bi < 4; bi++) {
                uint32_t bd = sb + b_off + bi * 16 * GS_ROWB + kb;
                ldsm_x4(bd, bh[bi][0], bh[bi][1], bh[bi][2], bh[bi][3]);
            }
#pragma unroll
            for (int mi = 0; mi < 4; mi++)
#pragma unroll
                for (int ni = 0; ni < 8; ni++)
                    mma_f16(acc[mi][ni], ah[mi],
                            bh[ni >> 1][(ni & 1) * 2], bh[ni >> 1][(ni & 1) * 2 + 1]);
#pragma unroll
            for (int mi = 0; mi < 4; mi++)
#pragma unroll
                for (int ni = 0; ni < 8; ni++)
                    mma_f16(acc[mi][ni], al[mi],
                            bh[ni >> 1][(ni & 1) * 2], bh[ni >> 1][(ni & 1) * 2 + 1]);
        }
    }

#pragma unroll
    for (int mi = 0; mi < 4; mi++) {
        const int r0 = m0 + wm + mi * 16 + (lane >> 2);
#pragma unroll
        for (int ni = 0; ni < 8; ni++) {
            const int c = n0 + wn + ni * 8 + (lane & 3) * 2;
            if (c < N) {
                float* p0 = C + (size_t)r0 * N + c;
                float* p1 = C + (size_t)(r0 + 8) * N + c;
                if (accum) {
                    atomicAdd(&p0[0], acc[mi][ni][0]);
                    atomicAdd(&p0[1], acc[mi][ni][1]);
                    atomicAdd(&p1[0], acc[mi][ni][2]);
                    atomicAdd(&p1[1], acc[mi][ni][3]);
                } else {
                    p0[0] = acc[mi][ni][0];
                    p0[1] = acc[mi][ni][1];
                    p1[0] = acc[mi][ni][2];
                    p1[1] = acc[mi][ni][3];
                }
            }
        }
    }
#undef FILL_STAGE
}

// =====================================================================
// Depthwise causal conv (k=4) + bias + SiLU (scalar)
// =====================================================================
__global__ __launch_bounds__(256) void conv_silu_kernel(
    const float* __restrict__ cw, const float* __restrict__ cb)
{
    int idx = blockIdx.x * blockDim.x + threadIdx.x;
    if (idx >= MROWS * CONVD) return;
    int c = idx % CONVD;
    int l = (idx / CONVD) % SEQLEN;
    int b = idx / (CONVD * SEQLEN);

    float acc = cb[c];
    const float* w = cw + c * DCONV;
#pragma unroll
    for (int j = 0; j < DCONV; j++) {
        int ls = l - (DCONV - 1) + j;
        if (ls >= 0)
            acc = fmaf(w[j], g_zx[(size_t)(b * SEQLEN + ls) * DPROJ + DINNER + c], acc);
    }
    g_xbc[idx] = acc / (1.f + expf(-acc));
}

// =====================================================================
// SSM scan, segmented (2 segments x 256 steps), 4-way state split.
// grid = 64bh x 2seg x 4sp = 512 blocks of 64 threads.
// Thread = p position; owns 32 states (16 f32x2 regs). B/C smem reads are
// warp-broadcast; no shuffles. seg0 stores final state; seg1 runs with
// zero init state + stores cumulative decay (fixed up by scan_correct).
// =====================================================================
#define SG2 4   // steps per prefetch group
__global__ __launch_bounds__(64) void ssm_scan_seg(
    const float* __restrict__ dt_bias, const float* __restrict__ A_log,
    const float* __restrict__ Dp)
{
    const int bid = blockIdx.x;
    const int sp  = bid & 3;
    const int seg = (bid >> 2) & 1;
    const int bh  = bid >> 3;
    const int b = bh >> 5, h = bh & 31;
    const int tid = threadIdx.x;     // = p (0..63)

    __shared__ __align__(16) float sh[2][SG2][128];  // x(64)|B(32)|C(32)
    __shared__ float2 sh_dta[2][SG2];

    unsigned long long s[16];
#pragma unroll
    for (int i = 0; i < 16; i++) s[i] = 0ULL;

    const float Aval = -expf(A_log[h]);
    const float dtb  = dt_bias[h];
    const float Dv   = Dp[h];

    const size_t row0 = (size_t)(b * SEQLEN + seg * SEGLEN);
    const float* xb = g_xbc + row0 * CONVD;
    const float* dtb_g = g_zx + row0 * DPROJ + DT_OFF + h;

    // two gmem columns per thread: col0 = x[p]; col1 = B or C slice element
    const float* colp0 = xb + h * HEADDIM + tid;
    const float* colp1 = (tid < 32)
        ? xb + DINNER + sp * 32 + tid
        : xb + DINNER + DSTATE + sp * 32 + (tid - 32);
    const int sidx1 = 64 + tid;   // smem slot for col1 (64..95 B, 96..127 C)

    float pre0[SG2], pre1[SG2];
#pragma unroll
    for (int q = 0; q < SG2; q++) {
        pre0[q] = colp0[(size_t)q * CONVD];
        pre1[q] = colp1[(size_t)q * CONVD];
    }
    float predt = (tid < SG2) ? dtb_g[(size_t)tid * DPROJ] : 0.f;

    float* yb = g_yp[sp] + row0 * DINNER + h * HEADDIM + tid;
    float cd_run = 1.f;
    const bool cd_writer = (sp == 0) && (seg == 1) && (tid == 0);

    for (int g = 0; g < SEGLEN / SG2; g++) {
        const int buf = g & 1;
#pragma unroll
        for (int q = 0; q < SG2; q++) {
            sh[buf][q][tid] = pre0[q];
            sh[buf][q][sidx1] = pre1[q];
        }
        if (tid < SG2) {
            const float dtr = predt + dtb;
            const float dtv = (dtr > 20.f) ? dtr : log1pf(expf(dtr));
            sh_dta[buf][tid] = make_float2(dtv, expf(dtv * Aval));
        }
        __syncthreads();

        if (g + 1 < SEGLEN / SG2) {
            const size_t l0 = (size_t)(g + 1) * SG2;
#pragma unroll
            for (int q = 0; q < SG2; q++) {
                pre0[q] = colp0[(l0 + q) * CONVD];
                pre1[q] = colp1[(l0 + q) * CONVD];
            }
            if (tid < SG2) predt = dtb_g[(l0 + tid) * DPROJ];
        }

#pragma unroll
        for (int q = 0; q < SG2; q++) {
            const float2 dta = sh_dta[buf][q];
            const float xv = sh[buf][q][tid];
            const float coef = dta.x * xv;
            unsigned long long coef2, dA2;
            F32X2_BCAST(coef2, coef);
            F32X2_BCAST(dA2, dta.y);

            unsigned long long acc2 = 0ULL;
#pragma unroll
            for (int v = 0; v < 8; v++) {
                const ulonglong2 Bp = *reinterpret_cast<const ulonglong2*>(
                    &sh[buf][q][64 + v * 4]);
                const ulonglong2 Cp = *reinterpret_cast<const ulonglong2*>(
                    &sh[buf][q][96 + v * 4]);
                unsigned long long t0, t1;
                F32X2_MUL(t0, coef2, Bp.x);
                F32X2_MUL(t1, coef2, Bp.y);
                F32X2_FMA(s[2 * v], dA2, t0);
                F32X2_FMA(s[2 * v + 1], dA2, t1);
                if (v == 0) F32X2_MUL(acc2, s[0], Cp.x);
                else        F32X2_FMA3(acc2, s[2 * v], Cp.x);
                F32X2_FMA3(acc2, s[2 * v + 1], Cp.y);
            }
            float alo, ahi;
            F32X2_UNPACK(alo, ahi, acc2);
            float acc = alo + ahi;
            if (sp == 0) acc = fmaf(Dv, xv, acc);
            yb[(size_t)(g * SG2 + q) * DINNER] = acc;

            if (cd_writer) {
                cd_run *= dta.y;
                g_cd[bh * SEGLEN + g * SG2 + q] = cd_run;
            }
        }
    }

    if (seg == 0) {
        float* sst = g_sstate + ((size_t)bh * HEADDIM + tid) * DSTATE + sp * 32;
#pragma unroll
        for (int v = 0; v < 16; v++) {
            float lo, hi;
            F32X2_UNPACK(lo, hi, s[v]);
            sst[2 * v] = lo;
            sst[2 * v + 1] = hi;
        }
    }
}

// =====================================================================
// Scan correction for segment 1: y_l += cd_l * (C_l . S_end_seg0)
// grid = 64bh x 4 (64-step quarters of seg1); 256 threads.
// =====================================================================
__global__ __launch_bounds__(256) void scan_correct()
{
    const int lq = blockIdx.x & 3;
    const int bh = blockIdx.x >> 2;
    const int b = bh >> 5, h = bh & 31;
    const int tid = threadIdx.x;

    __shared__ __align__(16) float Sst[64][132];  // padded rows (16B-mult)
    __shared__ __align__(16) float Cl[64][128];
    __shared__ float cd[64];

    // load S (8192 floats) via float4
    const float* sbase = g_sstate + (size_t)bh * HEADDIM * DSTATE;
    for (int i = tid; i < 2048; i += 256) {
        float4 v = *reinterpret_cast<const float4*>(&sbase[i * 4]);
        int r = i >> 5, c = (i & 31) * 4;
        *reinterpret_cast<float4*>(&Sst[r][c]) = v;
    }
    // load C rows for this quarter (8192 floats)
    const size_t row0 = (size_t)(b * SEQLEN + SEGLEN + lq * 64);
    for (int i = tid; i < 2048; i += 256) {
        int l = i >> 5, c = (i & 31) * 4;
        float4 v = *reinterpret_cast<const float4*>(
            &g_xbc[(row0 + l) * CONVD + DINNER + DSTATE + c]);
        *reinterpret_cast<float4*>(&Cl[l][c]) = v;
    }
    if (tid < 64) cd[tid] = g_cd[bh * SEGLEN + lq * 64 + tid];
    __syncthreads();

    const int p = tid & 63;
    const int lg = tid >> 6;    // 0..3, 16 l each

    unsigned long long accll[16];
#pragma unroll
    for (int i = 0; i < 16; i++) accll[i] = 0ULL;

    for (int n4 = 0; n4 < 32; n4++) {
        const ulonglong2 sv = *reinterpret_cast<const ulonglong2*>(
            &Sst[p][n4 * 4]);
#pragma unroll
        for (int i = 0; i < 16; i++) {
            const ulonglong2 cv = *reinterpret_cast<const ulonglong2*>(
                &Cl[lg * 16 + i][n4 * 4]);
            F32X2_FMA3(accll[i], cv.x, sv.x);
            F32X2_FMA3(accll[i], cv.y, sv.y);
        }
    }

#pragma unroll
    for (int i = 0; i < 16; i++) {
        const int l = lg * 16 + i;
        float lo, hi;
        F32X2_UNPACK(lo, hi, accll[i]);
        const float corr = (lo + hi) * cd[l];
        float* yp = g_yp[0] + (row0 + l) * DINNER + h * HEADDIM + p;
        *yp += corr;
    }
}

// =====================================================================
// Gated RMSNorm (sums 4 scan partials, float4 loads) -> fp16 hi/lo
// =====================================================================
__global__ __launch_bounds__(256) void gated_norm_kernel(
    const float* __restrict__ nw)
{
    const int row = blockIdx.x;
    const int tid = threadIdx.x;
    const int c0 = tid * 8;
    __shared__ float red[256];

    const size_t base = (size_t)row * DINNER + c0;
    float4 v0 = make_float4(0.f, 0.f, 0.f, 0.f);
    float4 v1 = v0;
#pragma unroll
    for (int k = 0; k < 4; k++) {
        float4 a = *reinterpret_cast<const float4*>(&g_yp[k][base]);
        float4 c = *reinterpret_cast<const float4*>(&g_yp[k][base + 4]);
        v0.x += a.x; v0.y += a.y; v0.z += a.z; v0.w += a.w;
        v1.x += c.x; v1.y += c.y; v1.z += c.z; v1.w += c.w;
    }
    const float4 z0 = *reinterpret_cast<const float4*>(
        &g_zx[(size_t)row * DPROJ + c0]);
    const float4 z1 = *reinterpret_cast<const float4*>(
        &g_zx[(size_t)row * DPROJ + c0 + 4]);

    float vals[8];
    vals[0] = v0.x * (z0.x / (1.f + expf(-z0.x)));
    vals[1] = v0.y * (z0.y / (1.f + expf(-z0.y)));
    vals[2] = v0.z * (z0.z / (1.f + expf(-z0.z)));
    vals[3] = v0.w * (z0.w / (1.f + expf(-z0.w)));
    vals[4] = v1.x * (z1.x / (1.f + expf(-z1.x)));
    vals[5] = v1.y * (z1.y / (1.f + expf(-z1.y)));
    vals[6] = v1.z * (z1.z / (1.f + expf(-z1.z)));
    vals[7] = v1.w * (z1.w / (1.f + expf(-z1.w)));

    float ss = 0.f;
#pragma unroll
    for (int i = 0; i < 8; i++) ss = fmaf(vals[i], vals[i], ss);

    red[tid] = ss;
    __syncthreads();
#pragma unroll
    for (int stride = 128; stride >= 32; stride >>= 1) {
        if (tid < stride) red[tid] += red[tid + stride];
        __syncthreads();
    }
    if (tid < 32) {
        float v = red[tid];
#pragma unroll
        for (int o = 16; o > 0; o >>= 1)
            v += __shfl_down_sync(0xffffffffu, v, o);
        if (tid == 0) red[0] = v;
    }
    __syncthreads();
    const float scale = rsqrtf(red[0] / (float)DINNER + 1e-5f);

    const float4 w0 = *reinterpret_cast<const float4*>(&nw[c0]);
    const float4 w1 = *reinterpret_cast<const float4*>(&nw[c0 + 4]);
    float o[8];
    o[0] = vals[0] * scale * w0.x;  o[1] = vals[1] * scale * w0.y;
    o[2] = vals[2] * scale * w0.z;  o[3] = vals[3] * scale * w0.w;
    o[4] = vals[4] * scale * w1.x;  o[5] = vals[5] * scale * w1.y;
    o[6] = vals[6] * scale * w1.z;  o[7] = vals[7] * scale * w1.w;

    uint4 hpack, lpack;
    float hh[8];
#pragma unroll
    for (int i = 0; i < 8; i++) hh[i] = __half2float(__float2half_rn(o[i]));
    hpack.x = pack_h2(o[0], o[1]);  hpack.y = pack_h2(o[2], o[3]);
    hpack.z = pack_h2(o[4], o[5]);  hpack.w = pack_h2(o[6], o[7]);
    lpack.x = pack_h2(o[0] - hh[0], o[1] - hh[1]);
    lpack.y = pack_h2(o[2] - hh[2], o[3] - hh[3]);
    lpack.z = pack_h2(o[4] - hh[4], o[5] - hh[5]);
    lpack.w = pack_h2(o[6] - hh[6], o[7] - hh[7]);
    *reinterpret_cast<uint4*>(&g_ynh[base]) = hpack;
    *reinterpret_cast<uint4*>(&g_ynl[base]) = lpack;
}

// =====================================================================
// launch
// =====================================================================
extern "C" void kernel_launch(void* const* d_in, const int* in_sizes, int n_in,
                              void* d_out, int out_size)
{
    const float* u       = (const float*)d_in[0];
    const float* W_in    = (const float*)d_in[1];
    const float* conv_w  = (const float*)d_in[2];
    const float* conv_b  = (const float*)d_in[3];
    const float* dt_bias = (const float*)d_in[4];
    const float* A_log   = (const float*)d_in[5];
    const float* D_param = (const float*)d_in[6];
    const float* norm_w  = (const float*)d_in[7];
    const float* W_out   = (const float*)d_in[8];
    float* out = (float*)d_out;

    float* zx;
    cudaGetSymbolAddress((void**)&zx, g_zx);
    __half *uh, *ul, *wih, *ynh, *ynl, *woh;
    cudaGetSymbolAddress((void**)&uh,  g_uh);
    cudaGetSymbolAddress((void**)&ul,  g_ul);
    cudaGetSymbolAddress((void**)&wih, g_wih);
    cudaGetSymbolAddress((void**)&ynh, g_ynh);
    cudaGetSymbolAddress((void**)&ynl, g_ynl);
    cudaGetSymbolAddress((void**)&woh, g_woh);

    cudaFuncSetAttribute(gemm_f16_2t,
                         cudaFuncAttributeMaxDynamicSharedMemorySize, GS_SMEM);

    // 0) merged vectorized conversions
    convert_all<<<(CVT_TOT / 4 + 255) / 256, 256>>>(u, W_in, W_out);

    // 1) in_proj: 18x8 = 144 CTAs
    {
        dim3 grid(NPAD / 256, MROWS / 128, 1);
        gemm_f16_2t<<<grid, 256, GS_SMEM>>>(uh, ul, wih, zx,
                                            MROWS, DPROJ, DMODEL, 0);
    }

    // 2) depthwise conv + silu
    {
        int total = MROWS * CONVD;
        conv_silu_kernel<<<(total + 255) / 256, 256>>>(conv_w, conv_b);
    }

    // 3a) segmented SSM scan: 64bh x 2seg x 4sp = 512 blocks of 64 threads
    ssm_scan_seg<<<64 * 2 * 4, 64>>>(dt_bias, A_log, D_param);

    // 3b) segment-1 state-carry correction: 64bh x 4 quarters
    scan_correct<<<64 * 4, 256>>>();

    // 4) gated RMSNorm (sums 4 partials, emits fp16 hi/lo)
    gated_norm_kernel<<<MROWS, 256>>>(norm_w);

    // 5) out_proj: split-K=4 -- 128 CTAs
    cudaMemsetAsync(out, 0, (size_t)out_size * sizeof(float));
    {
        dim3 grid(DMODEL / 256, MROWS / 128, 4);
        gemm_f16_2t<<<grid, 256, GS_SMEM>>>(ynh, ynl, woh, out,
                                            MROWS, DMODEL, DINNER, 1);
    }
}

// round 14
// speedup vs baseline: 1.0688x; 1.0688x over previous
#include <cuda_runtime.h>
#include <cuda_fp16.h>
#include <math.h>
#include <stdint.h>

// ---------------- problem constants ----------------
#define BATCH   2
#define SEQLEN  512
#define DMODEL  1024
#define DINNER  2048
#define NHEADS  32
#define HEADDIM 64
#define DSTATE  128
#define DCONV   4
#define DPROJ   4384   // 2*DINNER + 2*DSTATE + NHEADS
#define NPAD    4608   // DPROJ padded to multiple of 256
#define CONVD   2304   // DINNER + 2*DSTATE
#define MROWS   (BATCH*SEQLEN)   // 1024
#define DT_OFF  (DINNER + CONVD) // 4352
#define NSEG    8
#define SEGLEN  64               // SEQLEN / NSEG

// ---------------- scratch (static device memory) ----------------
__device__ float g_zx [MROWS * DPROJ];      // in_proj output  (1024 x 4384)
__device__ float g_xbc[MROWS * CONVD];      // conv+silu output
__device__ float g_yp [4][MROWS * DINNER];  // scan partial outputs (4 n-chunks)
__device__ float g_sloc  [64 * NSEG * HEADDIM * DSTATE];  // local seg-final states
__device__ float g_scarry[64 * NSEG * HEADDIM * DSTATE];  // chained start states
__device__ float g_cd[64 * NSEG * SEGLEN];  // per-step cumulative decay

__device__ __half g_uh [MROWS * DMODEL];
__device__ __half g_ul [MROWS * DMODEL];
__device__ __half g_wih[NPAD  * DMODEL];
__device__ __half g_ynh[MROWS * DINNER];
__device__ __half g_ynl[MROWS * DINNER];
__device__ __half g_woh[DMODEL * DINNER];

// =====================================================================
// helpers
// =====================================================================
__device__ __forceinline__ uint32_t smem_u32(const void* p) {
    uint32_t a;
    asm("{ .reg .u64 t; cvta.to.shared.u64 t, %1; cvt.u32.u64 %0, t; }"
        : "=r"(a) : "l"(p));
    return a;
}

__device__ __forceinline__ void cpa16(uint32_t dst, const void* src) {
    asm volatile("cp.async.cg.shared.global [%0], [%1], 16;"
                 :: "r"(dst), "l"(src) : "memory");
}
#define CP_COMMIT() asm volatile("cp.async.commit_group;" ::: "memory")

__device__ __forceinline__ void ldsm_x4(uint32_t addr, uint32_t& r0, uint32_t& r1,
                                        uint32_t& r2, uint32_t& r3) {
    asm volatile("ldmatrix.sync.aligned.m8n8.x4.shared.b16 {%0,%1,%2,%3}, [%4];"
                 : "=r"(r0), "=r"(r1), "=r"(r2), "=r"(r3) : "r"(addr));
}

__device__ __forceinline__ void mma_f16(float* c, const uint32_t* a,
                                        uint32_t b0, uint32_t b1) {
    asm volatile(
        "mma.sync.aligned.m16n8k16.row.col.f32.f16.f16.f32 "
        "{%0,%1,%2,%3}, {%4,%5,%6,%7}, {%8,%9}, {%0,%1,%2,%3};"
        : "+f"(c[0]), "+f"(c[1]), "+f"(c[2]), "+f"(c[3])
        : "r"(a[0]), "r"(a[1]), "r"(a[2]), "r"(a[3]), "r"(b0), "r"(b1));
}

__device__ __forceinline__ uint32_t pack_h2(float a, float b) {
    __half2 h = __floats2half2_rn(a, b);
    return *reinterpret_cast<uint32_t*>(&h);
}

#define F32X2_MUL(d, a, b) \
    asm("mul.rn.f32x2 %0, %1, %2;" : "=l"(d) : "l"(a), "l"(b))
#define F32X2_FMA(d, a, b) \
    asm("fma.rn.f32x2 %0, %0, %1, %2;" : "+l"(d) : "l"(a), "l"(b))
#define F32X2_FMA3(d, a, b) \
    asm("fma.rn.f32x2 %0, %1, %2, %0;" : "+l"(d) : "l"(a), "l"(b))
#define F32X2_BCAST(d, f) \
    asm("mov.b64 %0, {%1, %1};" : "=l"(d) : "f"(f))
#define F32X2_UNPACK(lo, hi, v) \
    asm("mov.b64 {%0, %1}, %2;" : "=f"(lo), "=f"(hi) : "l"(v))

// =====================================================================
// merged, vectorized fp32 -> fp16 conversions (u hi/lo, W_in hi, W_out hi)
// =====================================================================
#define CVT_N0 (MROWS * DMODEL)
#define CVT_N1 (NPAD * DMODEL)
#define CVT_N2 (DMODEL * DINNER)
#define CVT_TOT (CVT_N0 + CVT_N1 + CVT_N2)

__global__ __launch_bounds__(256) void convert_all(
    const float* __restrict__ u, const float* __restrict__ W_in,
    const float* __restrict__ W_out)
{
    int i = (blockIdx.x * 256 + threadIdx.x) * 4;
    if (i < CVT_N0) {
        float4 v = *reinterpret_cast<const float4*>(&u[i]);
        float hx = __half2float(__float2half_rn(v.x));
        float hy = __half2float(__float2half_rn(v.y));
        float hz = __half2float(__float2half_rn(v.z));
        float hw = __half2float(__float2half_rn(v.w));
        *reinterpret_cast<uint2*>(&g_uh[i]) =
            make_uint2(pack_h2(v.x, v.y), pack_h2(v.z, v.w));
        *reinterpret_cast<uint2*>(&g_ul[i]) =
            make_uint2(pack_h2(v.x - hx, v.y - hy), pack_h2(v.z - hz, v.w - hw));
    } else if (i < CVT_N0 + CVT_N1) {
        int j = i - CVT_N0;
        float4 v = make_float4(0.f, 0.f, 0.f, 0.f);
        if (j < DPROJ * DMODEL)
            v = *reinterpret_cast<const float4*>(&W_in[j]);
        *reinterpret_cast<uint2*>(&g_wih[j]) =
            make_uint2(pack_h2(v.x, v.y), pack_h2(v.z, v.w));
    } else if (i < CVT_TOT) {
        int j = i - CVT_N0 - CVT_N1;
        float4 v = *reinterpret_cast<const float4*>(&W_out[j]);
        *reinterpret_cast<uint2*>(&g_woh[j]) =
            make_uint2(pack_h2(v.x, v.y), pack_h2(v.z, v.w));
    }
}

// =====================================================================
// fp16 2-term split GEMM (NT) -- unchanged proven config
// =====================================================================
#define GS_ROWB 80
#define GS_STGB (512*GS_ROWB)
#define GS_SMEM (3*GS_STGB)
#define GS_AL_OFF (128*GS_ROWB)
#define GS_BH_OFF (256*GS_ROWB)

__global__ __launch_bounds__(256) void gemm_f16_2t(
    const __half* __restrict__ Ah, const __half* __restrict__ Al,
    const __half* __restrict__ Bh,
    float* __restrict__ C, int M, int N, int K, int accum)
{
    extern __shared__ char smem[];
    const uint32_t sbase = smem_u32(smem);
    const int tid = threadIdx.x;
    const int lane = tid & 31;
    const int warp = tid >> 5;
    const int wm = (warp >> 2) * 64;
    const int wn = (warp & 3) * 64;

    const int m0 = blockIdx.y * 128;
    const int n0 = blockIdx.x * 256;
    const int kslice = K / gridDim.z;
    const int kbeg = blockIdx.z * kslice;
    const int T = kslice / 32;

    float acc[4][8][4];
#pragma unroll
    for (int i = 0; i < 4; i++)
#pragma unroll
        for (int j = 0; j < 8; j++)
#pragma unroll
            for (int q = 0; q < 4; q++) acc[i][j][q] = 0.f;

    const __half* ptr0 = (tid < 128)
        ? Ah + (size_t)(m0 + tid) * K + kbeg
        : Al + (size_t)(m0 + tid - 128) * K + kbeg;
    const __half* ptr1 = Bh + (size_t)(n0 + tid) * K + kbeg;
    const uint32_t srow0 = sbase + tid * GS_ROWB;
    const uint32_t srow1 = sbase + (tid + 256) * GS_ROWB;

#define FILL_STAGE(STG, KOFF)                                                  \
    {                                                                          \
        uint32_t s0 = srow0 + (STG) * GS_STGB;                                 \
        uint32_t s1 = srow1 + (STG) * GS_STGB;                                 \
        _Pragma("unroll")                                                      \
        for (int sg = 0; sg < 4; sg++) {                                       \
            cpa16(s0 + sg * 16, ptr0 + (KOFF) + sg * 8);                       \
            cpa16(s1 + sg * 16, ptr1 + (KOFF) + sg * 8);                       \
        }                                                                      \
    }

    const uint32_t a_off = (uint32_t)((wm + (lane & 15)) * GS_ROWB + (lane >> 4) * 16);
    const uint32_t b_row = (uint32_t)(wn + ((lane >> 4) << 3) + (lane & 7));
    const uint32_t b_off = GS_BH_OFF + b_row * GS_ROWB + (((lane >> 3) & 1) << 4);

    FILL_STAGE(0, 0);
    CP_COMMIT();
    FILL_STAGE(1, 32);
    CP_COMMIT();

    for (int t = 0; t < T; t++) {
        asm volatile("cp.async.wait_group 1;" ::: "memory");
        __syncthreads();
        if (t + 2 < T) {
            int stg = (t + 2) % 3;
            FILL_STAGE(stg, (t + 2) * 32);
            CP_COMMIT();
        }

        const uint32_t sb = sbase + (t % 3) * GS_STGB;
#pragma unroll
        for (int ks = 0; ks < 2; ks++) {
            const uint32_t kb = ks * 32;
            uint32_t ah[4][4], al[4][4], bh[4][4];
#pragma unroll
            for (int mi = 0; mi < 4; mi++) {
                uint32_t ad = sb + a_off + mi * 16 * GS_ROWB + kb;
                ldsm_x4(ad, ah[mi][0], ah[mi][1], ah[mi][2], ah[mi][3]);
                ldsm_x4(ad + GS_AL_OFF, al[mi][0], al[mi][1], al[mi][2], al[mi][3]);
            }
#pragma unroll
            for (int bi = 0; bi < 4; bi++) {
                uint32_t bd = sb + b_off + bi * 16 * GS_ROWB + kb;
                ldsm_x4(bd, bh[bi][0], bh[bi][1], bh[bi][2], bh[bi][3]);
            }
#pragma unroll
            for (int mi = 0; mi < 4; mi++)
#pragma unroll
                for (int ni = 0; ni < 8; ni++)
                    mma_f16(acc[mi][ni], ah[mi],
                            bh[ni >> 1][(ni & 1) * 2], bh[ni >> 1][(ni & 1) * 2 + 1]);
#pragma unroll
            for (int mi = 0; mi < 4; mi++)
#pragma unroll
                for (int ni = 0; ni < 8; ni++)
                    mma_f16(acc[mi][ni], al[mi],
                            bh[ni >> 1][(ni & 1) * 2], bh[ni >> 1][(ni & 1) * 2 + 1]);
        }
    }

#pragma unroll
    for (int mi = 0; mi < 4; mi++) {
        const int r0 = m0 + wm + mi * 16 + (lane >> 2);
#pragma unroll
        for (int ni = 0; ni < 8; ni++) {
            const int c = n0 + wn + ni * 8 + (lane & 3) * 2;
            if (c < N) {
                float* p0 = C + (size_t)r0 * N + c;
                float* p1 = C + (size_t)(r0 + 8) * N + c;
                if (accum) {
                    atomicAdd(&p0[0], acc[mi][ni][0]);
                    atomicAdd(&p0[1], acc[mi][ni][1]);
                    atomicAdd(&p1[0], acc[mi][ni][2]);
                    atomicAdd(&p1[1], acc[mi][ni][3]);
                } else {
                    p0[0] = acc[mi][ni][0];
                    p0[1] = acc[mi][ni][1];
                    p1[0] = acc[mi][ni][2];
                    p1[1] = acc[mi][ni][3];
                }
            }
        }
    }
#undef FILL_STAGE
}

// =====================================================================
// Depthwise causal conv (k=4) + bias + SiLU (scalar)
// =====================================================================
__global__ __launch_bounds__(256) void conv_silu_kernel(
    const float* __restrict__ cw, const float* __restrict__ cb)
{
    int idx = blockIdx.x * blockDim.x + threadIdx.x;
    if (idx >= MROWS * CONVD) return;
    int c = idx % CONVD;
    int l = (idx / CONVD) % SEQLEN;
    int b = idx / (CONVD * SEQLEN);

    float acc = cb[c];
    const float* w = cw + c * DCONV;
#pragma unroll
    for (int j = 0; j < DCONV; j++) {
        int ls = l - (DCONV - 1) + j;
        if (ls >= 0)
            acc = fmaf(w[j], g_zx[(size_t)(b * SEQLEN + ls) * DPROJ + DINNER + c], acc);
    }
    g_xbc[idx] = acc / (1.f + expf(-acc));
}

// =====================================================================
// SSM scan, 8 segments x 64 steps, 4-way state split.
// grid = 64bh x 8seg x 4sp = 2048 blocks of 64 threads.
// Thread = p position; owns 32 states (16 f32x2 regs). B/C smem reads are
// warp-broadcast; no shuffles. Each seg runs with zero init; stores local
// final state (segs 0..6) and per-step cumulative decay (sp==0 writer).
// =====================================================================
#define SG2 4   // steps per prefetch group
__global__ __launch_bounds__(64) void ssm_scan_seg(
    const float* __restrict__ dt_bias, const float* __restrict__ A_log,
    const float* __restrict__ Dp)
{
    const int bid = blockIdx.x;
    const int sp  = bid & 3;
    const int seg = (bid >> 2) & 7;
    const int bh  = bid >> 5;
    const int b = bh >> 5, h = bh & 31;
    const int tid = threadIdx.x;     // = p (0..63)

    __shared__ __align__(16) float sh[2][SG2][128];  // x(64)|B(32)|C(32)
    __shared__ float2 sh_dta[2][SG2];

    unsigned long long s[16];
#pragma unroll
    for (int i = 0; i < 16; i++) s[i] = 0ULL;

    const float Aval = -expf(A_log[h]);
    const float dtb  = dt_bias[h];
    const float Dv   = Dp[h];

    const size_t row0 = (size_t)(b * SEQLEN + seg * SEGLEN);
    const float* xb = g_xbc + row0 * CONVD;
    const float* dtb_g = g_zx + row0 * DPROJ + DT_OFF + h;

    const float* colp0 = xb + h * HEADDIM + tid;
    const float* colp1 = (tid < 32)
        ? xb + DINNER + sp * 32 + tid
        : xb + DINNER + DSTATE + sp * 32 + (tid - 32);
    const int sidx1 = 64 + tid;

    float pre0[SG2], pre1[SG2];
#pragma unroll
    for (int q = 0; q < SG2; q++) {
        pre0[q] = colp0[(size_t)q * CONVD];
        pre1[q] = colp1[(size_t)q * CONVD];
    }
    float predt = (tid < SG2) ? dtb_g[(size_t)tid * DPROJ] : 0.f;

    float* yb = g_yp[sp] + row0 * DINNER + h * HEADDIM + tid;
    float cd_run = 1.f;
    const bool cd_writer = (sp == 0) && (tid == 0);

    for (int g = 0; g < SEGLEN / SG2; g++) {
        const int buf = g & 1;
#pragma unroll
        for (int q = 0; q < SG2; q++) {
            sh[buf][q][tid] = pre0[q];
            sh[buf][q][sidx1] = pre1[q];
        }
        if (tid < SG2) {
            const float dtr = predt + dtb;
            const float dtv = (dtr > 20.f) ? dtr : log1pf(expf(dtr));
            sh_dta[buf][tid] = make_float2(dtv, expf(dtv * Aval));
        }
        __syncthreads();

        if (g + 1 < SEGLEN / SG2) {
            const size_t l0 = (size_t)(g + 1) * SG2;
#pragma unroll
            for (int q = 0; q < SG2; q++) {
                pre0[q] = colp0[(l0 + q) * CONVD];
                pre1[q] = colp1[(l0 + q) * CONVD];
            }
            if (tid < SG2) predt = dtb_g[(l0 + tid) * DPROJ];
        }

#pragma unroll
        for (int q = 0; q < SG2; q++) {
            const float2 dta = sh_dta[buf][q];
            const float xv = sh[buf][q][tid];
            const float coef = dta.x * xv;
            unsigned long long coef2, dA2;
            F32X2_BCAST(coef2, coef);
            F32X2_BCAST(dA2, dta.y);

            unsigned long long acc2 = 0ULL;
#pragma unroll
            for (int v = 0; v < 8; v++) {
                const ulonglong2 Bp = *reinterpret_cast<const ulonglong2*>(
                    &sh[buf][q][64 + v * 4]);
                const ulonglong2 Cp = *reinterpret_cast<const ulonglong2*>(
                    &sh[buf][q][96 + v * 4]);
                unsigned long long t0, t1;
                F32X2_MUL(t0, coef2, Bp.x);
                F32X2_MUL(t1, coef2, Bp.y);
                F32X2_FMA(s[2 * v], dA2, t0);
                F32X2_FMA(s[2 * v + 1], dA2, t1);
                if (v == 0) F32X2_MUL(acc2, s[0], Cp.x);
                else        F32X2_FMA3(acc2, s[2 * v], Cp.x);
                F32X2_FMA3(acc2, s[2 * v + 1], Cp.y);
            }
            float alo, ahi;
            F32X2_UNPACK(alo, ahi, acc2);
            float acc = alo + ahi;
            if (sp == 0) acc = fmaf(Dv, xv, acc);
            yb[(size_t)(g * SG2 + q) * DINNER] = acc;

            if (cd_writer) {
                cd_run *= dta.y;
                g_cd[(bh * NSEG + seg) * SEGLEN + g * SG2 + q] = cd_run;
            }
        }
    }

    if (seg < NSEG - 1) {
        float* sst = g_sloc + (((size_t)bh * NSEG + seg) * HEADDIM + tid) * DSTATE
                   + sp * 32;
#pragma unroll
        for (int v = 0; v < 16; v++) {
            float lo, hi;
            F32X2_UNPACK(lo, hi, s[v]);
            sst[2 * v] = lo;
            sst[2 * v + 1] = hi;
        }
    }
}

// =====================================================================
// State chain: S_in(0)=0; S_in(j+1) = D_j * S_in(j) + Sloc_j.
// grid = 64bh x 8 p-groups; 256 threads; one float4 per thread per seg.
// =====================================================================
__global__ __launch_bounds__(256) void scan_chain()
{
    const int pg = blockIdx.x & 7;       // p group (8 p rows)
    const int bh = blockIdx.x >> 3;
    const int tid = threadIdx.x;
    const int p = pg * 8 + (tid >> 5);
    const int n4 = (tid & 31) * 4;

    const size_t eoff = ((size_t)p) * DSTATE + n4;
    const size_t segstride = (size_t)HEADDIM * DSTATE;
    const float* sloc = g_sloc + (size_t)bh * NSEG * segstride + eoff;
    float* scar = g_scarry + (size_t)bh * NSEG * segstride + eoff;

    float4 carry = make_float4(0.f, 0.f, 0.f, 0.f);
#pragma unroll
    for (int j = 0; j < NSEG; j++) {
        *reinterpret_cast<float4*>(scar + (size_t)j * segstride) = carry;
        if (j < NSEG - 1) {
            const float D = g_cd[(bh * NSEG + j) * SEGLEN + SEGLEN - 1];
            const float4 sl = *reinterpret_cast<const float4*>(
                sloc + (size_t)j * segstride);
            carry.x = fmaf(D, carry.x, sl.x);
            carry.y = fmaf(D, carry.y, sl.y);
            carry.z = fmaf(D, carry.z, sl.z);
            carry.w = fmaf(D, carry.w, sl.w);
        }
    }
}

// =====================================================================
// Correction for segments 1..7: y_l += cd_l * (C_l . S_in(seg))
// grid = 64bh x 7; 256 threads.
// =====================================================================
__global__ __launch_bounds__(256) void scan_correct()
{
    const int sg1 = blockIdx.x % 7;      // 0..6 -> seg 1..7
    const int seg = sg1 + 1;
    const int bh = blockIdx.x / 7;
    const int b = bh >> 5, h = bh & 31;
    const int tid = threadIdx.x;

    __shared__ __align__(16) float Sst[64][132];
    __shared__ __align__(16) float Cl[64][128];
    __shared__ float cd[64];

    const float* sbase = g_scarry
        + ((size_t)bh * NSEG + seg) * HEADDIM * DSTATE;
    for (int i = tid; i < 2048; i += 256) {
        float4 v = *reinterpret_cast<const float4*>(&sbase[i * 4]);
        int r = i >> 5, c = (i & 31) * 4;
        *reinterpret_cast<float4*>(&Sst[r][c]) = v;
    }
    const size_t row0 = (size_t)(b * SEQLEN + seg * SEGLEN);
    for (int i = tid; i < 2048; i += 256) {
        int l = i >> 5, c = (i & 31) * 4;
        float4 v = *reinterpret_cast<const float4*>(
            &g_xbc[(row0 + l) * CONVD + DINNER + DSTATE + c]);
        *reinterpret_cast<float4*>(&Cl[l][c]) = v;
    }
    if (tid < 64) cd[tid] = g_cd[(bh * NSEG + seg) * SEGLEN + tid];
    __syncthreads();

    const int p = tid & 63;
    const int lg = tid >> 6;

    unsigned long long accll[16];
#pragma unroll
    for (int i = 0; i < 16; i++) accll[i] = 0ULL;

    for (int n4 = 0; n4 < 32; n4++) {
        const ulonglong2 sv = *reinterpret_cast<const ulonglong2*>(
            &Sst[p][n4 * 4]);
#pragma unroll
        for (int i = 0; i < 16; i++) {
            const ulonglong2 cv = *reinterpret_cast<const ulonglong2*>(
                &Cl[lg * 16 + i][n4 * 4]);
            F32X2_FMA3(accll[i], cv.x, sv.x);
            F32X2_FMA3(accll[i], cv.y, sv.y);
        }
    }

#pragma unroll
    for (int i = 0; i < 16; i++) {
        const int l = lg * 16 + i;
        float lo, hi;
        F32X2_UNPACK(lo, hi, accll[i]);
        const float corr = (lo + hi) * cd[l];
        float* yp = g_yp[0] + (row0 + l) * DINNER + h * HEADDIM + p;
        *yp += corr;
    }
}

// =====================================================================
// Gated RMSNorm (sums 4 scan partials, float4 loads) -> fp16 hi/lo
// =====================================================================
__global__ __launch_bounds__(256) void gated_norm_kernel(
    const float* __restrict__ nw)
{
    const int row = blockIdx.x;
    const int tid = threadIdx.x;
    const int c0 = tid * 8;
    __shared__ float red[256];

    const size_t base = (size_t)row * DINNER + c0;
    float4 v0 = make_float4(0.f, 0.f, 0.f, 0.f);
    float4 v1 = v0;
#pragma unroll
    for (int k = 0; k < 4; k++) {
        float4 a = *reinterpret_cast<const float4*>(&g_yp[k][base]);
        float4 c = *reinterpret_cast<const float4*>(&g_yp[k][base + 4]);
        v0.x += a.x; v0.y += a.y; v0.z += a.z; v0.w += a.w;
        v1.x += c.x; v1.y += c.y; v1.z += c.z; v1.w += c.w;
    }
    const float4 z0 = *reinterpret_cast<const float4*>(
        &g_zx[(size_t)row * DPROJ + c0]);
    const float4 z1 = *reinterpret_cast<const float4*>(
        &g_zx[(size_t)row * DPROJ + c0 + 4]);

    float vals[8];
    vals[0] = v0.x * (z0.x / (1.f + expf(-z0.x)));
    vals[1] = v0.y * (z0.y / (1.f + expf(-z0.y)));
    vals[2] = v0.z * (z0.z / (1.f + expf(-z0.z)));
    vals[3] = v0.w * (z0.w / (1.f + expf(-z0.w)));
    vals[4] = v1.x * (z1.x / (1.f + expf(-z1.x)));
    vals[5] = v1.y * (z1.y / (1.f + expf(-z1.y)));
    vals[6] = v1.z * (z1.z / (1.f + expf(-z1.z)));
    vals[7] = v1.w * (z1.w / (1.f + expf(-z1.w)));

    float ss = 0.f;
#pragma unroll
    for (int i = 0; i < 8; i++) ss = fmaf(vals[i], vals[i], ss);

    red[tid] = ss;
    __syncthreads();
#pragma unroll
    for (int stride = 128; stride >= 32; stride >>= 1) {
        if (tid < stride) red[tid] += red[tid + stride];
        __syncthreads();
    }
    if (tid < 32) {
        float v = red[tid];
#pragma unroll
        for (int o = 16; o > 0; o >>= 1)
            v += __shfl_down_sync(0xffffffffu, v, o);
        if (tid == 0) red[0] = v;
    }
    __syncthreads();
    const float scale = rsqrtf(red[0] / (float)DINNER + 1e-5f);

    const float4 w0 = *reinterpret_cast<const float4*>(&nw[c0]);
    const float4 w1 = *reinterpret_cast<const float4*>(&nw[c0 + 4]);
    float o[8];
    o[0] = vals[0] * scale * w0.x;  o[1] = vals[1] * scale * w0.y;
    o[2] = vals[2] * scale * w0.z;  o[3] = vals[3] * scale * w0.w;
    o[4] = vals[4] * scale * w1.x;  o[5] = vals[5] * scale * w1.y;
    o[6] = vals[6] * scale * w1.z;  o[7] = vals[7] * scale * w1.w;

    uint4 hpack, lpack;
    float hh[8];
#pragma unroll
    for (int i = 0; i < 8; i++) hh[i] = __half2float(__float2half_rn(o[i]));
    hpack.x = pack_h2(o[0], o[1]);  hpack.y = pack_h2(o[2], o[3]);
    hpack.z = pack_h2(o[4], o[5]);  hpack.w = pack_h2(o[6], o[7]);
    lpack.x = pack_h2(o[0] - hh[0], o[1] - hh[1]);
    lpack.y = pack_h2(o[2] - hh[2], o[3] - hh[3]);
    lpack.z = pack_h2(o[4] - hh[4], o[5] - hh[5]);
    lpack.w = pack_h2(o[6] - hh[6], o[7] - hh[7]);
    *reinterpret_cast<uint4*>(&g_ynh[base]) = hpack;
    *reinterpret_cast<uint4*>(&g_ynl[base]) = lpack;
}

// =====================================================================
// launch
// =====================================================================
extern "C" void kernel_launch(void* const* d_in, const int* in_sizes, int n_in,
                              void* d_out, int out_size)
{
    const float* u       = (const float*)d_in[0];
    const float* W_in    = (const float*)d_in[1];
    const float* conv_w  = (const float*)d_in[2];
    const float* conv_b  = (const float*)d_in[3];
    const float* dt_bias = (const float*)d_in[4];
    const float* A_log   = (const float*)d_in[5];
    const float* D_param = (const float*)d_in[6];
    const float* norm_w  = (const float*)d_in[7];
    const float* W_out   = (const float*)d_in[8];
    float* out = (float*)d_out;

    float* zx;
    cudaGetSymbolAddress((void**)&zx, g_zx);
    __half *uh, *ul, *wih, *ynh, *ynl, *woh;
    cudaGetSymbolAddress((void**)&uh,  g_uh);
    cudaGetSymbolAddress((void**)&ul,  g_ul);
    cudaGetSymbolAddress((void**)&wih, g_wih);
    cudaGetSymbolAddress((void**)&ynh, g_ynh);
    cudaGetSymbolAddress((void**)&ynl, g_ynl);
    cudaGetSymbolAddress((void**)&woh, g_woh);

    cudaFuncSetAttribute(gemm_f16_2t,
                         cudaFuncAttributeMaxDynamicSharedMemorySize, GS_SMEM);

    // 0) merged vectorized conversions
    convert_all<<<(CVT_TOT / 4 + 255) / 256, 256>>>(u, W_in, W_out);

    // 1) in_proj: 18x8 = 144 CTAs
    {
        dim3 grid(NPAD / 256, MROWS / 128, 1);
        gemm_f16_2t<<<grid, 256, GS_SMEM>>>(uh, ul, wih, zx,
                                            MROWS, DPROJ, DMODEL, 0);
    }

    // 2) depthwise conv + silu
    {
        int total = MROWS * CONVD;
        conv_silu_kernel<<<(total + 255) / 256, 256>>>(conv_w, conv_b);
    }

    // 3a) segmented SSM scan: 64bh x 8seg x 4sp = 2048 blocks of 64 threads
    ssm_scan_seg<<<64 * NSEG * 4, 64>>>(dt_bias, A_log, D_param);

    // 3b) state chain across segments
    scan_chain<<<64 * 8, 256>>>();

    // 3c) state-carry correction for segments 1..7
    scan_correct<<<64 * 7, 256>>>();

    // 4) gated RMSNorm (sums 4 partials, emits fp16 hi/lo)
    gated_norm_kernel<<<MROWS, 256>>>(norm_w);

    // 5) out_proj: split-K=4 -- 128 CTAs
    cudaMemsetAsync(out, 0, (size_t)out_size * sizeof(float));
    {
        dim3 grid(DMODEL / 256, MROWS / 128, 4);
        gemm_f16_2t<<<grid, 256, GS_SMEM>>>(ynh, ynl, woh, out,
                                            MROWS, DMODEL, DINNER, 1);
    }
}

// round 15
// speedup vs baseline: 1.1272x; 1.0547x over previous
#include <cuda_runtime.h>
#include <cuda_fp16.h>
#include <math.h>
#include <stdint.h>

// ---------------- problem constants ----------------
#define BATCH   2
#define SEQLEN  512
#define DMODEL  1024
#define DINNER  2048
#define NHEADS  32
#define HEADDIM 64
#define DSTATE  128
#define DCONV   4
#define DPROJ   4384   // 2*DINNER + 2*DSTATE + NHEADS
#define NPAD    4608   // DPROJ padded to multiple of 256
#define CONVD   2304   // DINNER + 2*DSTATE
#define MROWS   (BATCH*SEQLEN)   // 1024
#define DT_OFF  (DINNER + CONVD) // 4352
#define NSEG    8
#define SEGLEN  64               // SEQLEN / NSEG

// ---------------- scratch (static device memory) ----------------
__device__ float g_zx [MROWS * DPROJ];      // in_proj output  (1024 x 4384)
__device__ float g_xbc[MROWS * CONVD];      // conv+silu output
__device__ float g_yp [4][MROWS * DINNER];  // scan partial outputs (4 n-chunks)
__device__ float g_sloc  [64 * NSEG * HEADDIM * DSTATE];  // local seg-final states
__device__ float g_scarry[64 * NSEG * HEADDIM * DSTATE];  // chained start states
__device__ float g_cd[64 * NSEG * SEGLEN];  // per-step cumulative decay

__device__ __half g_uh [MROWS * DMODEL];
__device__ __half g_ul [MROWS * DMODEL];
__device__ __half g_wih[NPAD  * DMODEL];
__device__ __half g_ynh[MROWS * DINNER];
__device__ __half g_woh[DMODEL * DINNER];

// =====================================================================
// helpers
// =====================================================================
__device__ __forceinline__ uint32_t smem_u32(const void* p) {
    uint32_t a;
    asm("{ .reg .u64 t; cvta.to.shared.u64 t, %1; cvt.u32.u64 %0, t; }"
        : "=r"(a) : "l"(p));
    return a;
}

__device__ __forceinline__ void cpa16(uint32_t dst, const void* src) {
    asm volatile("cp.async.cg.shared.global [%0], [%1], 16;"
                 :: "r"(dst), "l"(src) : "memory");
}
#define CP_COMMIT() asm volatile("cp.async.commit_group;" ::: "memory")

__device__ __forceinline__ void ldsm_x4(uint32_t addr, uint32_t& r0, uint32_t& r1,
                                        uint32_t& r2, uint32_t& r3) {
    asm volatile("ldmatrix.sync.aligned.m8n8.x4.shared.b16 {%0,%1,%2,%3}, [%4];"
                 : "=r"(r0), "=r"(r1), "=r"(r2), "=r"(r3) : "r"(addr));
}

__device__ __forceinline__ void mma_f16(float* c, const uint32_t* a,
                                        uint32_t b0, uint32_t b1) {
    asm volatile(
        "mma.sync.aligned.m16n8k16.row.col.f32.f16.f16.f32 "
        "{%0,%1,%2,%3}, {%4,%5,%6,%7}, {%8,%9}, {%0,%1,%2,%3};"
        : "+f"(c[0]), "+f"(c[1]), "+f"(c[2]), "+f"(c[3])
        : "r"(a[0]), "r"(a[1]), "r"(a[2]), "r"(a[3]), "r"(b0), "r"(b1));
}

__device__ __forceinline__ uint32_t pack_h2(float a, float b) {
    __half2 h = __floats2half2_rn(a, b);
    return *reinterpret_cast<uint32_t*>(&h);
}

#define F32X2_MUL(d, a, b) \
    asm("mul.rn.f32x2 %0, %1, %2;" : "=l"(d) : "l"(a), "l"(b))
#define F32X2_FMA(d, a, b) \
    asm("fma.rn.f32x2 %0, %0, %1, %2;" : "+l"(d) : "l"(a), "l"(b))
#define F32X2_FMA3(d, a, b) \
    asm("fma.rn.f32x2 %0, %1, %2, %0;" : "+l"(d) : "l"(a), "l"(b))
#define F32X2_BCAST(d, f) \
    asm("mov.b64 %0, {%1, %1};" : "=l"(d) : "f"(f))
#define F32X2_UNPACK(lo, hi, v) \
    asm("mov.b64 {%0, %1}, %2;" : "=f"(lo), "=f"(hi) : "l"(v))

// =====================================================================
// merged, vectorized fp32 -> fp16 conversions (u hi/lo, W_in hi, W_out hi)
// =====================================================================
#define CVT_N0 (MROWS * DMODEL)
#define CVT_N1 (NPAD * DMODEL)
#define CVT_N2 (DMODEL * DINNER)
#define CVT_TOT (CVT_N0 + CVT_N1 + CVT_N2)

__global__ __launch_bounds__(256) void convert_all(
    const float* __restrict__ u, const float* __restrict__ W_in,
    const float* __restrict__ W_out)
{
    int i = (blockIdx.x * 256 + threadIdx.x) * 4;
    if (i < CVT_N0) {
        float4 v = *reinterpret_cast<const float4*>(&u[i]);
        float hx = __half2float(__float2half_rn(v.x));
        float hy = __half2float(__float2half_rn(v.y));
        float hz = __half2float(__float2half_rn(v.z));
        float hw = __half2float(__float2half_rn(v.w));
        *reinterpret_cast<uint2*>(&g_uh[i]) =
            make_uint2(pack_h2(v.x, v.y), pack_h2(v.z, v.w));
        *reinterpret_cast<uint2*>(&g_ul[i]) =
            make_uint2(pack_h2(v.x - hx, v.y - hy), pack_h2(v.z - hz, v.w - hw));
    } else if (i < CVT_N0 + CVT_N1) {
        int j = i - CVT_N0;
        float4 v = make_float4(0.f, 0.f, 0.f, 0.f);
        if (j < DPROJ * DMODEL)
            v = *reinterpret_cast<const float4*>(&W_in[j]);
        *reinterpret_cast<uint2*>(&g_wih[j]) =
            make_uint2(pack_h2(v.x, v.y), pack_h2(v.z, v.w));
    } else if (i < CVT_TOT) {
        int j = i - CVT_N0 - CVT_N1;
        float4 v = *reinterpret_cast<const float4*>(&W_out[j]);
        *reinterpret_cast<uint2*>(&g_woh[j]) =
            make_uint2(pack_h2(v.x, v.y), pack_h2(v.z, v.w));
    }
}

// =====================================================================
// fp16 split GEMM (NT): C[m,n] = sum_k A[m,k]*B[n,k]
// two_term=1: C = Ah*Bh + Al*Bh;  two_term=0: C = Ah*Bh only.
// CTA 128x256, 8 warps, warp tile 64x64, BK=32, 3-stage cp.async.
// =====================================================================
#define GS_ROWB 80
#define GS_STGB (512*GS_ROWB)
#define GS_SMEM (3*GS_STGB)
#define GS_AL_OFF (128*GS_ROWB)
#define GS_BH_OFF (256*GS_ROWB)

__global__ __launch_bounds__(256) void gemm_f16_2t(
    const __half* __restrict__ Ah, const __half* __restrict__ Al,
    const __half* __restrict__ Bh,
    float* __restrict__ C, int M, int N, int K, int accum, int two_term)
{
    extern __shared__ char smem[];
    const uint32_t sbase = smem_u32(smem);
    const int tid = threadIdx.x;
    const int lane = tid & 31;
    const int warp = tid >> 5;
    const int wm = (warp >> 2) * 64;
    const int wn = (warp & 3) * 64;

    const int m0 = blockIdx.y * 128;
    const int n0 = blockIdx.x * 256;
    const int kslice = K / gridDim.z;
    const int kbeg = blockIdx.z * kslice;
    const int T = kslice / 32;

    float acc[4][8][4];
#pragma unroll
    for (int i = 0; i < 4; i++)
#pragma unroll
        for (int j = 0; j < 8; j++)
#pragma unroll
            for (int q = 0; q < 4; q++) acc[i][j][q] = 0.f;

    const __half* ptr0 = (tid < 128)
        ? Ah + (size_t)(m0 + tid) * K + kbeg
        : Al + (size_t)(m0 + tid - 128) * K + kbeg;
    const __half* ptr1 = Bh + (size_t)(n0 + tid) * K + kbeg;
    const uint32_t srow0 = sbase + tid * GS_ROWB;
    const uint32_t srow1 = sbase + (tid + 256) * GS_ROWB;
    const bool fill0 = two_term || (tid < 128);

#define FILL_STAGE(STG, KOFF)                                                  \
    {                                                                          \
        uint32_t s0 = srow0 + (STG) * GS_STGB;                                 \
        uint32_t s1 = srow1 + (STG) * GS_STGB;                                 \
        _Pragma("unroll")                                                      \
        for (int sg = 0; sg < 4; sg++) {                                       \
            if (fill0) cpa16(s0 + sg * 16, ptr0 + (KOFF) + sg * 8);            \
            cpa16(s1 + sg * 16, ptr1 + (KOFF) + sg * 8);                       \
        }                                                                      \
    }

    const uint32_t a_off = (uint32_t)((wm + (lane & 15)) * GS_ROWB + (lane >> 4) * 16);
    const uint32_t b_row = (uint32_t)(wn + ((lane >> 4) << 3) + (lane & 7));
    const uint32_t b_off = GS_BH_OFF + b_row * GS_ROWB + (((lane >> 3) & 1) << 4);

    FILL_STAGE(0, 0);
    CP_COMMIT();
    FILL_STAGE(1, 32);
    CP_COMMIT();

    for (int t = 0; t < T; t++) {
        asm volatile("cp.async.wait_group 1;" ::: "memory");
        __syncthreads();
        if (t + 2 < T) {
            int stg = (t + 2) % 3;
            FILL_STAGE(stg, (t + 2) * 32);
            CP_COMMIT();
        }

        const uint32_t sb = sbase + (t % 3) * GS_STGB;
#pragma unroll
        for (int ks = 0; ks < 2; ks++) {
            const uint32_t kb = ks * 32;
            uint32_t ah[4][4], al[4][4], bh[4][4];
#pragma unroll
            for (int mi = 0; mi < 4; mi++) {
                uint32_t ad = sb + a_off + mi * 16 * GS_ROWB + kb;
                ldsm_x4(ad, ah[mi][0], ah[mi][1], ah[mi][2], ah[mi][3]);
                if (two_term)
                    ldsm_x4(ad + GS_AL_OFF, al[mi][0], al[mi][1], al[mi][2], al[mi][3]);
            }
#pragma unroll
            for (int bi = 0; bi < 4; bi++) {
                uint32_t bd = sb + b_off + bi * 16 * GS_ROWB + kb;
                ldsm_x4(bd, bh[bi][0], bh[bi][1], bh[bi][2], bh[bi][3]);
            }
#pragma unroll
            for (int mi = 0; mi < 4; mi++)
#pragma unroll
                for (int ni = 0; ni < 8; ni++)
                    mma_f16(acc[mi][ni], ah[mi],
                            bh[ni >> 1][(ni & 1) * 2], bh[ni >> 1][(ni & 1) * 2 + 1]);
            if (two_term) {
#pragma unroll
                for (int mi = 0; mi < 4; mi++)
#pragma unroll
                    for (int ni = 0; ni < 8; ni++)
                        mma_f16(acc[mi][ni], al[mi],
                                bh[ni >> 1][(ni & 1) * 2], bh[ni >> 1][(ni & 1) * 2 + 1]);
            }
        }
    }

#pragma unroll
    for (int mi = 0; mi < 4; mi++) {
        const int r0 = m0 + wm + mi * 16 + (lane >> 2);
#pragma unroll
        for (int ni = 0; ni < 8; ni++) {
            const int c = n0 + wn + ni * 8 + (lane & 3) * 2;
            if (c < N) {
                float* p0 = C + (size_t)r0 * N + c;
                float* p1 = C + (size_t)(r0 + 8) * N + c;
                if (accum) {
                    atomicAdd(&p0[0], acc[mi][ni][0]);
                    atomicAdd(&p0[1], acc[mi][ni][1]);
                    atomicAdd(&p1[0], acc[mi][ni][2]);
                    atomicAdd(&p1[1], acc[mi][ni][3]);
                } else {
                    p0[0] = acc[mi][ni][0];
                    p0[1] = acc[mi][ni][1];
                    p1[0] = acc[mi][ni][2];
                    p1[1] = acc[mi][ni][3];
                }
            }
        }
    }
#undef FILL_STAGE
}

// =====================================================================
// Depthwise causal conv (k=4) + bias + SiLU.
// Thread computes 4 consecutive l for one channel: 7 loads / 4 outputs.
// =====================================================================
__global__ __launch_bounds__(256) void conv_silu_kernel(
    const float* __restrict__ cw, const float* __restrict__ cb)
{
    int idx = blockIdx.x * blockDim.x + threadIdx.x;
    if (idx >= (MROWS / 4) * CONVD) return;
    const int c = idx % CONVD;
    const int lq = idx / CONVD;
    const int l0 = (lq & (SEQLEN / 4 - 1)) * 4;
    const int b = lq / (SEQLEN / 4);

    const float w0 = cw[c * DCONV + 0];
    const float w1 = cw[c * DCONV + 1];
    const float w2 = cw[c * DCONV + 2];
    const float w3 = cw[c * DCONV + 3];
    const float bias = cb[c];

    const float* zb = g_zx + (size_t)(b * SEQLEN) * DPROJ + DINNER + c;
    float v[7];
#pragma unroll
    for (int j = 0; j < 7; j++) {
        const int l = l0 - 3 + j;
        v[j] = (l >= 0) ? zb[(size_t)l * DPROJ] : 0.f;
    }

    float* ob = g_xbc + (size_t)(b * SEQLEN + l0) * CONVD + c;
#pragma unroll
    for (int q = 0; q < 4; q++) {
        float a = bias;
        a = fmaf(w0, v[q], a);
        a = fmaf(w1, v[q + 1], a);
        a = fmaf(w2, v[q + 2], a);
        a = fmaf(w3, v[q + 3], a);
        ob[(size_t)q * CONVD] = a / (1.f + expf(-a));
    }
}

// =====================================================================
// SSM scan, 8 segments x 64 steps, 4-way state split (R14 proven).
// =====================================================================
#define SG2 4
__global__ __launch_bounds__(64) void ssm_scan_seg(
    const float* __restrict__ dt_bias, const float* __restrict__ A_log,
    const float* __restrict__ Dp)
{
    const int bid = blockIdx.x;
    const int sp  = bid & 3;
    const int seg = (bid >> 2) & 7;
    const int bh  = bid >> 5;
    const int b = bh >> 5, h = bh & 31;
    const int tid = threadIdx.x;

    __shared__ __align__(16) float sh[2][SG2][128];
    __shared__ float2 sh_dta[2][SG2];

    unsigned long long s[16];
#pragma unroll
    for (int i = 0; i < 16; i++) s[i] = 0ULL;

    const float Aval = -expf(A_log[h]);
    const float dtb  = dt_bias[h];
    const float Dv   = Dp[h];

    const size_t row0 = (size_t)(b * SEQLEN + seg * SEGLEN);
    const float* xb = g_xbc + row0 * CONVD;
    const float* dtb_g = g_zx + row0 * DPROJ + DT_OFF + h;

    const float* colp0 = xb + h * HEADDIM + tid;
    const float* colp1 = (tid < 32)
        ? xb + DINNER + sp * 32 + tid
        : xb + DINNER + DSTATE + sp * 32 + (tid - 32);
    const int sidx1 = 64 + tid;

    float pre0[SG2], pre1[SG2];
#pragma unroll
    for (int q = 0; q < SG2; q++) {
        pre0[q] = colp0[(size_t)q * CONVD];
        pre1[q] = colp1[(size_t)q * CONVD];
    }
    float predt = (tid < SG2) ? dtb_g[(size_t)tid * DPROJ] : 0.f;

    float* yb = g_yp[sp] + row0 * DINNER + h * HEADDIM + tid;
    float cd_run = 1.f;
    const bool cd_writer = (sp == 0) && (tid == 0);

    for (int g = 0; g < SEGLEN / SG2; g++) {
        const int buf = g & 1;
#pragma unroll
        for (int q = 0; q < SG2; q++) {
            sh[buf][q][tid] = pre0[q];
            sh[buf][q][sidx1] = pre1[q];
        }
        if (tid < SG2) {
            const float dtr = predt + dtb;
            const float dtv = (dtr > 20.f) ? dtr : log1pf(expf(dtr));
            sh_dta[buf][tid] = make_float2(dtv, expf(dtv * Aval));
        }
        __syncthreads();

        if (g + 1 < SEGLEN / SG2) {
            const size_t l0 = (size_t)(g + 1) * SG2;
#pragma unroll
            for (int q = 0; q < SG2; q++) {
                pre0[q] = colp0[(l0 + q) * CONVD];
                pre1[q] = colp1[(l0 + q) * CONVD];
            }
            if (tid < SG2) predt = dtb_g[(l0 + tid) * DPROJ];
        }

#pragma unroll
        for (int q = 0; q < SG2; q++) {
            const float2 dta = sh_dta[buf][q];
            const float xv = sh[buf][q][tid];
            const float coef = dta.x * xv;
            unsigned long long coef2, dA2;
            F32X2_BCAST(coef2, coef);
            F32X2_BCAST(dA2, dta.y);

            unsigned long long acc2 = 0ULL;
#pragma unroll
            for (int v = 0; v < 8; v++) {
                const ulonglong2 Bp = *reinterpret_cast<const ulonglong2*>(
                    &sh[buf][q][64 + v * 4]);
                const ulonglong2 Cp = *reinterpret_cast<const ulonglong2*>(
                    &sh[buf][q][96 + v * 4]);
                unsigned long long t0, t1;
                F32X2_MUL(t0, coef2, Bp.x);
                F32X2_MUL(t1, coef2, Bp.y);
                F32X2_FMA(s[2 * v], dA2, t0);
                F32X2_FMA(s[2 * v + 1], dA2, t1);
                if (v == 0) F32X2_MUL(acc2, s[0], Cp.x);
                else        F32X2_FMA3(acc2, s[2 * v], Cp.x);
                F32X2_FMA3(acc2, s[2 * v + 1], Cp.y);
            }
            float alo, ahi;
            F32X2_UNPACK(alo, ahi, acc2);
            float acc = alo + ahi;
            if (sp == 0) acc = fmaf(Dv, xv, acc);
            yb[(size_t)(g * SG2 + q) * DINNER] = acc;

            if (cd_writer) {
                cd_run *= dta.y;
                g_cd[(bh * NSEG + seg) * SEGLEN + g * SG2 + q] = cd_run;
            }
        }
    }

    if (seg < NSEG - 1) {
        float* sst = g_sloc + (((size_t)bh * NSEG + seg) * HEADDIM + tid) * DSTATE
                   + sp * 32;
#pragma unroll
        for (int v = 0; v < 16; v++) {
            float lo, hi;
            F32X2_UNPACK(lo, hi, s[v]);
            sst[2 * v] = lo;
            sst[2 * v + 1] = hi;
        }
    }
}

// =====================================================================
// State chain: S_in(0)=0; S_in(j+1) = D_j * S_in(j) + Sloc_j.
// =====================================================================
__global__ __launch_bounds__(256) void scan_chain()
{
    const int pg = blockIdx.x & 7;
    const int bh = blockIdx.x >> 3;
    const int tid = threadIdx.x;
    const int p = pg * 8 + (tid >> 5);
    const int n4 = (tid & 31) * 4;

    const size_t eoff = ((size_t)p) * DSTATE + n4;
    const size_t segstride = (size_t)HEADDIM * DSTATE;
    const float* sloc = g_sloc + (size_t)bh * NSEG * segstride + eoff;
    float* scar = g_scarry + (size_t)bh * NSEG * segstride + eoff;

    float4 carry = make_float4(0.f, 0.f, 0.f, 0.f);
#pragma unroll
    for (int j = 0; j < NSEG; j++) {
        *reinterpret_cast<float4*>(scar + (size_t)j * segstride) = carry;
        if (j < NSEG - 1) {
            const float D = g_cd[(bh * NSEG + j) * SEGLEN + SEGLEN - 1];
            const float4 sl = *reinterpret_cast<const float4*>(
                sloc + (size_t)j * segstride);
            carry.x = fmaf(D, carry.x, sl.x);
            carry.y = fmaf(D, carry.y, sl.y);
            carry.z = fmaf(D, carry.z, sl.z);
            carry.w = fmaf(D, carry.w, sl.w);
        }
    }
}

// =====================================================================
// Correction for segments 1..7: y_l += cd_l * (C_l . S_in(seg))
// =====================================================================
__global__ __launch_bounds__(256) void scan_correct()
{
    const int sg1 = blockIdx.x % 7;
    const int seg = sg1 + 1;
    const int bh = blockIdx.x / 7;
    const int b = bh >> 5, h = bh & 31;
    const int tid = threadIdx.x;

    __shared__ __align__(16) float Sst[64][132];
    __shared__ __align__(16) float Cl[64][128];
    __shared__ float cd[64];

    const float* sbase = g_scarry
        + ((size_t)bh * NSEG + seg) * HEADDIM * DSTATE;
    for (int i = tid; i < 2048; i += 256) {
        float4 v = *reinterpret_cast<const float4*>(&sbase[i * 4]);
        int r = i >> 5, c = (i & 31) * 4;
        *reinterpret_cast<float4*>(&Sst[r][c]) = v;
    }
    const size_t row0 = (size_t)(b * SEQLEN + seg * SEGLEN);
    for (int i = tid; i < 2048; i += 256) {
        int l = i >> 5, c = (i & 31) * 4;
        float4 v = *reinterpret_cast<const float4*>(
            &g_xbc[(row0 + l) * CONVD + DINNER + DSTATE + c]);
        *reinterpret_cast<float4*>(&Cl[l][c]) = v;
    }
    if (tid < 64) cd[tid] = g_cd[(bh * NSEG + seg) * SEGLEN + tid];
    __syncthreads();

    const int p = tid & 63;
    const int lg = tid >> 6;

    unsigned long long accll[16];
#pragma unroll
    for (int i = 0; i < 16; i++) accll[i] = 0ULL;

    for (int n4 = 0; n4 < 32; n4++) {
        const ulonglong2 sv = *reinterpret_cast<const ulonglong2*>(
            &Sst[p][n4 * 4]);
#pragma unroll
        for (int i = 0; i < 16; i++) {
            const ulonglong2 cv = *reinterpret_cast<const ulonglong2*>(
                &Cl[lg * 16 + i][n4 * 4]);
            F32X2_FMA3(accll[i], cv.x, sv.x);
            F32X2_FMA3(accll[i], cv.y, sv.y);
        }
    }

#pragma unroll
    for (int i = 0; i < 16; i++) {
        const int l = lg * 16 + i;
        float lo, hi;
        F32X2_UNPACK(lo, hi, accll[i]);
        const float corr = (lo + hi) * cd[l];
        float* yp = g_yp[0] + (row0 + l) * DINNER + h * HEADDIM + p;
        *yp += corr;
    }
}

// =====================================================================
// Gated RMSNorm (sums 4 scan partials, float4 loads) -> fp16 hi only
// =====================================================================
__global__ __launch_bounds__(256) void gated_norm_kernel(
    const float* __restrict__ nw)
{
    const int row = blockIdx.x;
    const int tid = threadIdx.x;
    const int c0 = tid * 8;
    __shared__ float red[256];

    const size_t base = (size_t)row * DINNER + c0;
    float4 v0 = make_float4(0.f, 0.f, 0.f, 0.f);
    float4 v1 = v0;
#pragma unroll
    for (int k = 0; k < 4; k++) {
        float4 a = *reinterpret_cast<const float4*>(&g_yp[k][base]);
        float4 c = *reinterpret_cast<const float4*>(&g_yp[k][base + 4]);
        v0.x += a.x; v0.y += a.y; v0.z += a.z; v0.w += a.w;
        v1.x += c.x; v1.y += c.y; v1.z += c.z; v1.w += c.w;
    }
    const float4 z0 = *reinterpret_cast<const float4*>(
        &g_zx[(size_t)row * DPROJ + c0]);
    const float4 z1 = *reinterpret_cast<const float4*>(
        &g_zx[(size_t)row * DPROJ + c0 + 4]);

    float vals[8];
    vals[0] = v0.x * (z0.x / (1.f + expf(-z0.x)));
    vals[1] = v0.y * (z0.y / (1.f + expf(-z0.y)));
    vals[2] = v0.z * (z0.z / (1.f + expf(-z0.z)));
    vals[3] = v0.w * (z0.w / (1.f + expf(-z0.w)));
    vals[4] = v1.x * (z1.x / (1.f + expf(-z1.x)));
    vals[5] = v1.y * (z1.y / (1.f + expf(-z1.y)));
    vals[6] = v1.z * (z1.z / (1.f + expf(-z1.z)));
    vals[7] = v1.w * (z1.w / (1.f + expf(-z1.w)));

    float ss = 0.f;
#pragma unroll
    for (int i = 0; i < 8; i++) ss = fmaf(vals[i], vals[i], ss);

    red[tid] = ss;
    __syncthreads();
#pragma unroll
    for (int stride = 128; stride >= 32; stride >>= 1) {
        if (tid < stride) red[tid] += red[tid + stride];
        __syncthreads();
    }
    if (tid < 32) {
        float v = red[tid];
#pragma unroll
        for (int o = 16; o > 0; o >>= 1)
            v += __shfl_down_sync(0xffffffffu, v, o);
        if (tid == 0) red[0] = v;
    }
    __syncthreads();
    const float scale = rsqrtf(red[0] / (float)DINNER + 1e-5f);

    const float4 w0 = *reinterpret_cast<const float4*>(&nw[c0]);
    const float4 w1 = *reinterpret_cast<const float4*>(&nw[c0 + 4]);
    float o[8];
    o[0] = vals[0] * scale * w0.x;  o[1] = vals[1] * scale * w0.y;
    o[2] = vals[2] * scale * w0.z;  o[3] = vals[3] * scale * w0.w;
    o[4] = vals[4] * scale * w1.x;  o[5] = vals[5] * scale * w1.y;
    o[6] = vals[6] * scale * w1.z;  o[7] = vals[7] * scale * w1.w;

    uint4 hpack;
    hpack.x = pack_h2(o[0], o[1]);  hpack.y = pack_h2(o[2], o[3]);
    hpack.z = pack_h2(o[4], o[5]);  hpack.w = pack_h2(o[6], o[7]);
    *reinterpret_cast<uint4*>(&g_ynh[base]) = hpack;
}

// =====================================================================
// launch
// =====================================================================
extern "C" void kernel_launch(void* const* d_in, const int* in_sizes, int n_in,
                              void* d_out, int out_size)
{
    const float* u       = (const float*)d_in[0];
    const float* W_in    = (const float*)d_in[1];
    const float* conv_w  = (const float*)d_in[2];
    const float* conv_b  = (const float*)d_in[3];
    const float* dt_bias = (const float*)d_in[4];
    const float* A_log   = (const float*)d_in[5];
    const float* D_param = (const float*)d_in[6];
    const float* norm_w  = (const float*)d_in[7];
    const float* W_out   = (const float*)d_in[8];
    float* out = (float*)d_out;

    float* zx;
    cudaGetSymbolAddress((void**)&zx, g_zx);
    __half *uh, *ul, *wih, *ynh, *woh;
    cudaGetSymbolAddress((void**)&uh,  g_uh);
    cudaGetSymbolAddress((void**)&ul,  g_ul);
    cudaGetSymbolAddress((void**)&wih, g_wih);
    cudaGetSymbolAddress((void**)&ynh, g_ynh);
    cudaGetSymbolAddress((void**)&woh, g_woh);

    cudaFuncSetAttribute(gemm_f16_2t,
                         cudaFuncAttributeMaxDynamicSharedMemorySize, GS_SMEM);

    // 0) merged vectorized conversions
    convert_all<<<(CVT_TOT / 4 + 255) / 256, 256>>>(u, W_in, W_out);

    // 1) in_proj (2-term): 18x8 = 144 CTAs
    {
        dim3 grid(NPAD / 256, MROWS / 128, 1);
        gemm_f16_2t<<<grid, 256, GS_SMEM>>>(uh, ul, wih, zx,
                                            MROWS, DPROJ, DMODEL, 0, 1);
    }

    // 2) depthwise conv + silu (4 l per thread)
    {
        int total = (MROWS / 4) * CONVD;
        conv_silu_kernel<<<(total + 255) / 256, 256>>>(conv_w, conv_b);
    }

    // 3a) segmented SSM scan: 2048 blocks of 64 threads
    ssm_scan_seg<<<64 * NSEG * 4, 64>>>(dt_bias, A_log, D_param);

    // 3b) state chain across segments
    scan_chain<<<64 * 8, 256>>>();

    // 3c) state-carry correction for segments 1..7
    scan_correct<<<64 * 7, 256>>>();

    // 4) gated RMSNorm (sums 4 partials, emits fp16 hi only)
    gated_norm_kernel<<<MROWS, 256>>>(norm_w);

    // 5) out_proj (single-term fp16): split-K=4 -- 128 CTAs
    cudaMemsetAsync(out, 0, (size_t)out_size * sizeof(float));
    {
        dim3 grid(DMODEL / 256, MROWS / 128, 4);
        gemm_f16_2t<<<grid, 256, GS_SMEM>>>(ynh, ynh, woh, out,
                                            MROWS, DMODEL, DINNER, 1, 0);
    }
}

// round 16
// speedup vs baseline: 1.1524x; 1.0223x over previous
#include <cuda_runtime.h>
#include <cuda_fp16.h>
#include <math.h>
#include <stdint.h>

// ---------------- problem constants ----------------
#define BATCH   2
#define SEQLEN  512
#define DMODEL  1024
#define DINNER  2048
#define NHEADS  32
#define HEADDIM 64
#define DSTATE  128
#define DCONV   4
#define DPROJ   4384   // 2*DINNER + 2*DSTATE + NHEADS
#define NPAD    4608   // DPROJ padded to multiple of 256
#define CONVD   2304   // DINNER + 2*DSTATE
#define MROWS   (BATCH*SEQLEN)   // 1024
#define DT_OFF  (DINNER + CONVD) // 4352
#define NSEG    8
#define SEGLEN  64               // SEQLEN / NSEG

// ---------------- scratch (static device memory) ----------------
__device__ float g_zx [MROWS * DPROJ];      // in_proj output  (1024 x 4384)
__device__ float g_xbc[MROWS * CONVD];      // conv+silu output
__device__ float g_yp [4][MROWS * DINNER];  // scan partial outputs (4 n-chunks)
__device__ float g_sloc  [64 * NSEG * HEADDIM * DSTATE];  // local seg-final states
__device__ float g_scarry[64 * NSEG * HEADDIM * DSTATE];  // chained start states
__device__ float g_cd[64 * NSEG * SEGLEN];  // per-step cumulative decay

__device__ __half g_uh [MROWS * DMODEL];
__device__ __half g_ul [MROWS * DMODEL];
__device__ __half g_wih[NPAD  * DMODEL];
__device__ __half g_ynh[MROWS * DINNER];
__device__ __half g_woh[DMODEL * DINNER];

// =====================================================================
// helpers
// =====================================================================
__device__ __forceinline__ uint32_t smem_u32(const void* p) {
    uint32_t a;
    asm("{ .reg .u64 t; cvta.to.shared.u64 t, %1; cvt.u32.u64 %0, t; }"
        : "=r"(a) : "l"(p));
    return a;
}

__device__ __forceinline__ void cpa16(uint32_t dst, const void* src) {
    asm volatile("cp.async.cg.shared.global [%0], [%1], 16;"
                 :: "r"(dst), "l"(src) : "memory");
}
#define CP_COMMIT() asm volatile("cp.async.commit_group;" ::: "memory")

__device__ __forceinline__ void ldsm_x4(uint32_t addr, uint32_t& r0, uint32_t& r1,
                                        uint32_t& r2, uint32_t& r3) {
    asm volatile("ldmatrix.sync.aligned.m8n8.x4.shared.b16 {%0,%1,%2,%3}, [%4];"
                 : "=r"(r0), "=r"(r1), "=r"(r2), "=r"(r3) : "r"(addr));
}

__device__ __forceinline__ void mma_f16(float* c, const uint32_t* a,
                                        uint32_t b0, uint32_t b1) {
    asm volatile(
        "mma.sync.aligned.m16n8k16.row.col.f32.f16.f16.f32 "
        "{%0,%1,%2,%3}, {%4,%5,%6,%7}, {%8,%9}, {%0,%1,%2,%3};"
        : "+f"(c[0]), "+f"(c[1]), "+f"(c[2]), "+f"(c[3])
        : "r"(a[0]), "r"(a[1]), "r"(a[2]), "r"(a[3]), "r"(b0), "r"(b1));
}

__device__ __forceinline__ uint32_t pack_h2(float a, float b) {
    __half2 h = __floats2half2_rn(a, b);
    return *reinterpret_cast<uint32_t*>(&h);
}

#define F32X2_MUL(d, a, b) \
    asm("mul.rn.f32x2 %0, %1, %2;" : "=l"(d) : "l"(a), "l"(b))
#define F32X2_FMA(d, a, b) \
    asm("fma.rn.f32x2 %0, %0, %1, %2;" : "+l"(d) : "l"(a), "l"(b))
#define F32X2_FMA3(d, a, b) \
    asm("fma.rn.f32x2 %0, %1, %2, %0;" : "+l"(d) : "l"(a), "l"(b))
#define F32X2_BCAST(d, f) \
    asm("mov.b64 %0, {%1, %1};" : "=l"(d) : "f"(f))
#define F32X2_UNPACK(lo, hi, v) \
    asm("mov.b64 {%0, %1}, %2;" : "=f"(lo), "=f"(hi) : "l"(v))

// =====================================================================
// merged, vectorized fp32 -> fp16 conversions (u hi/lo, W_in hi, W_out hi)
// =====================================================================
#define CVT_N0 (MROWS * DMODEL)
#define CVT_N1 (NPAD * DMODEL)
#define CVT_N2 (DMODEL * DINNER)
#define CVT_TOT (CVT_N0 + CVT_N1 + CVT_N2)

__global__ __launch_bounds__(256) void convert_all(
    const float* __restrict__ u, const float* __restrict__ W_in,
    const float* __restrict__ W_out)
{
    int i = (blockIdx.x * 256 + threadIdx.x) * 4;
    if (i < CVT_N0) {
        float4 v = *reinterpret_cast<const float4*>(&u[i]);
        float hx = __half2float(__float2half_rn(v.x));
        float hy = __half2float(__float2half_rn(v.y));
        float hz = __half2float(__float2half_rn(v.z));
        float hw = __half2float(__float2half_rn(v.w));
        *reinterpret_cast<uint2*>(&g_uh[i]) =
            make_uint2(pack_h2(v.x, v.y), pack_h2(v.z, v.w));
        *reinterpret_cast<uint2*>(&g_ul[i]) =
            make_uint2(pack_h2(v.x - hx, v.y - hy), pack_h2(v.z - hz, v.w - hw));
    } else if (i < CVT_N0 + CVT_N1) {
        int j = i - CVT_N0;
        float4 v = make_float4(0.f, 0.f, 0.f, 0.f);
        if (j < DPROJ * DMODEL)
            v = *reinterpret_cast<const float4*>(&W_in[j]);
        *reinterpret_cast<uint2*>(&g_wih[j]) =
            make_uint2(pack_h2(v.x, v.y), pack_h2(v.z, v.w));
    } else if (i < CVT_TOT) {
        int j = i - CVT_N0 - CVT_N1;
        float4 v = *reinterpret_cast<const float4*>(&W_out[j]);
        *reinterpret_cast<uint2*>(&g_woh[j]) =
            make_uint2(pack_h2(v.x, v.y), pack_h2(v.z, v.w));
    }
}

// =====================================================================
// fp16 split GEMM (NT): C[m,n] = sum_k A[m,k]*B[n,k]
// mode=0: single-term (Ah*Bh); mode=1: 2-term (Ah*Bh + Al*Bh);
// mode=2: 2-term ONLY in the last x-tile (selective precision for dt).
// CTA 128x256, 8 warps, warp tile 64x64, BK=32, 3-stage cp.async.
// =====================================================================
#define GS_ROWB 80
#define GS_STGB (512*GS_ROWB)
#define GS_SMEM (3*GS_STGB)
#define GS_AL_OFF (128*GS_ROWB)
#define GS_BH_OFF (256*GS_ROWB)

__global__ __launch_bounds__(256) void gemm_f16_2t(
    const __half* __restrict__ Ah, const __half* __restrict__ Al,
    const __half* __restrict__ Bh,
    float* __restrict__ C, int M, int N, int K, int accum, int mode)
{
    extern __shared__ char smem[];
    const uint32_t sbase = smem_u32(smem);
    const int tid = threadIdx.x;
    const int lane = tid & 31;
    const int warp = tid >> 5;
    const int wm = (warp >> 2) * 64;
    const int wn = (warp & 3) * 64;

    const int two_term = (mode == 1) ||
                         (mode == 2 && blockIdx.x == gridDim.x - 1);

    const int m0 = blockIdx.y * 128;
    const int n0 = blockIdx.x * 256;
    const int kslice = K / gridDim.z;
    const int kbeg = blockIdx.z * kslice;
    const int T = kslice / 32;

    float acc[4][8][4];
#pragma unroll
    for (int i = 0; i < 4; i++)
#pragma unroll
        for (int j = 0; j < 8; j++)
#pragma unroll
            for (int q = 0; q < 4; q++) acc[i][j][q] = 0.f;

    const __half* ptr0 = (tid < 128)
        ? Ah + (size_t)(m0 + tid) * K + kbeg
        : Al + (size_t)(m0 + tid - 128) * K + kbeg;
    const __half* ptr1 = Bh + (size_t)(n0 + tid) * K + kbeg;
    const uint32_t srow0 = sbase + tid * GS_ROWB;
    const uint32_t srow1 = sbase + (tid + 256) * GS_ROWB;
    const bool fill0 = two_term || (tid < 128);

#define FILL_STAGE(STG, KOFF)                                                  \
    {                                                                          \
        uint32_t s0 = srow0 + (STG) * GS_STGB;                                 \
        uint32_t s1 = srow1 + (STG) * GS_STGB;                                 \
        _Pragma("unroll")                                                      \
        for (int sg = 0; sg < 4; sg++) {                                       \
            if (fill0) cpa16(s0 + sg * 16, ptr0 + (KOFF) + sg * 8);            \
            cpa16(s1 + sg * 16, ptr1 + (KOFF) + sg * 8);                       \
        }                                                                      \
    }

    const uint32_t a_off = (uint32_t)((wm + (lane & 15)) * GS_ROWB + (lane >> 4) * 16);
    const uint32_t b_row = (uint32_t)(wn + ((lane >> 4) << 3) + (lane & 7));
    const uint32_t b_off = GS_BH_OFF + b_row * GS_ROWB + (((lane >> 3) & 1) << 4);

    FILL_STAGE(0, 0);
    CP_COMMIT();
    FILL_STAGE(1, 32);
    CP_COMMIT();

    for (int t = 0; t < T; t++) {
        asm volatile("cp.async.wait_group 1;" ::: "memory");
        __syncthreads();
        if (t + 2 < T) {
            int stg = (t + 2) % 3;
            FILL_STAGE(stg, (t + 2) * 32);
            CP_COMMIT();
        }

        const uint32_t sb = sbase + (t % 3) * GS_STGB;
#pragma unroll
        for (int ks = 0; ks < 2; ks++) {
            const uint32_t kb = ks * 32;
            uint32_t ah[4][4], al[4][4], bh[4][4];
#pragma unroll
            for (int mi = 0; mi < 4; mi++) {
                uint32_t ad = sb + a_off + mi * 16 * GS_ROWB + kb;
                ldsm_x4(ad, ah[mi][0], ah[mi][1], ah[mi][2], ah[mi][3]);
                if (two_term)
                    ldsm_x4(ad + GS_AL_OFF, al[mi][0], al[mi][1], al[mi][2], al[mi][3]);
            }
#pragma unroll
            for (int bi = 0; bi < 4; bi++) {
                uint32_t bd = sb + b_off + bi * 16 * GS_ROWB + kb;
                ldsm_x4(bd, bh[bi][0], bh[bi][1], bh[bi][2], bh[bi][3]);
            }
#pragma unroll
            for (int mi = 0; mi < 4; mi++)
#pragma unroll
                for (int ni = 0; ni < 8; ni++)
                    mma_f16(acc[mi][ni], ah[mi],
                            bh[ni >> 1][(ni & 1) * 2], bh[ni >> 1][(ni & 1) * 2 + 1]);
            if (two_term) {
#pragma unroll
                for (int mi = 0; mi < 4; mi++)
#pragma unroll
                    for (int ni = 0; ni < 8; ni++)
                        mma_f16(acc[mi][ni], al[mi],
                                bh[ni >> 1][(ni & 1) * 2], bh[ni >> 1][(ni & 1) * 2 + 1]);
            }
        }
    }

#pragma unroll
    for (int mi = 0; mi < 4; mi++) {
        const int r0 = m0 + wm + mi * 16 + (lane >> 2);
#pragma unroll
        for (int ni = 0; ni < 8; ni++) {
            const int c = n0 + wn + ni * 8 + (lane & 3) * 2;
            if (c < N) {
                float* p0 = C + (size_t)r0 * N + c;
                float* p1 = C + (size_t)(r0 + 8) * N + c;
                if (accum) {
                    atomicAdd(&p0[0], acc[mi][ni][0]);
                    atomicAdd(&p0[1], acc[mi][ni][1]);
                    atomicAdd(&p1[0], acc[mi][ni][2]);
                    atomicAdd(&p1[1], acc[mi][ni][3]);
                } else {
                    p0[0] = acc[mi][ni][0];
                    p0[1] = acc[mi][ni][1];
                    p1[0] = acc[mi][ni][2];
                    p1[1] = acc[mi][ni][3];
                }
            }
        }
    }
#undef FILL_STAGE
}

// =====================================================================
// Depthwise causal conv (k=4) + bias + SiLU.
// Thread computes 4 consecutive l for one channel: 7 loads / 4 outputs.
// =====================================================================
__global__ __launch_bounds__(256) void conv_silu_kernel(
    const float* __restrict__ cw, const float* __restrict__ cb)
{
    int idx = blockIdx.x * blockDim.x + threadIdx.x;
    if (idx >= (MROWS / 4) * CONVD) return;
    const int c = idx % CONVD;
    const int lq = idx / CONVD;
    const int l0 = (lq & (SEQLEN / 4 - 1)) * 4;
    const int b = lq / (SEQLEN / 4);

    const float w0 = cw[c * DCONV + 0];
    const float w1 = cw[c * DCONV + 1];
    const float w2 = cw[c * DCONV + 2];
    const float w3 = cw[c * DCONV + 3];
    const float bias = cb[c];

    const float* zb = g_zx + (size_t)(b * SEQLEN) * DPROJ + DINNER + c;
    float v[7];
#pragma unroll
    for (int j = 0; j < 7; j++) {
        const int l = l0 - 3 + j;
        v[j] = (l >= 0) ? zb[(size_t)l * DPROJ] : 0.f;
    }

    float* ob = g_xbc + (size_t)(b * SEQLEN + l0) * CONVD + c;
#pragma unroll
    for (int q = 0; q < 4; q++) {
        float a = bias;
        a = fmaf(w0, v[q], a);
        a = fmaf(w1, v[q + 1], a);
        a = fmaf(w2, v[q + 2], a);
        a = fmaf(w3, v[q + 3], a);
        ob[(size_t)q * CONVD] = a / (1.f + expf(-a));
    }
}

// =====================================================================
// SSM scan, 8 segments x 64 steps, 4-way state split (R14/R15 proven).
// =====================================================================
#define SG2 4
__global__ __launch_bounds__(64) void ssm_scan_seg(
    const float* __restrict__ dt_bias, const float* __restrict__ A_log,
    const float* __restrict__ Dp)
{
    const int bid = blockIdx.x;
    const int sp  = bid & 3;
    const int seg = (bid >> 2) & 7;
    const int bh  = bid >> 5;
    const int b = bh >> 5, h = bh & 31;
    const int tid = threadIdx.x;

    __shared__ __align__(16) float sh[2][SG2][128];
    __shared__ float2 sh_dta[2][SG2];

    unsigned long long s[16];
#pragma unroll
    for (int i = 0; i < 16; i++) s[i] = 0ULL;

    const float Aval = -expf(A_log[h]);
    const float dtb  = dt_bias[h];
    const float Dv   = Dp[h];

    const size_t row0 = (size_t)(b * SEQLEN + seg * SEGLEN);
    const float* xb = g_xbc + row0 * CONVD;
    const float* dtb_g = g_zx + row0 * DPROJ + DT_OFF + h;

    const float* colp0 = xb + h * HEADDIM + tid;
    const float* colp1 = (tid < 32)
        ? xb + DINNER + sp * 32 + tid
        : xb + DINNER + DSTATE + sp * 32 + (tid - 32);
    const int sidx1 = 64 + tid;

    float pre0[SG2], pre1[SG2];
#pragma unroll
    for (int q = 0; q < SG2; q++) {
        pre0[q] = colp0[(size_t)q * CONVD];
        pre1[q] = colp1[(size_t)q * CONVD];
    }
    float predt = (tid < SG2) ? dtb_g[(size_t)tid * DPROJ] : 0.f;

    float* yb = g_yp[sp] + row0 * DINNER + h * HEADDIM + tid;
    float cd_run = 1.f;
    const bool cd_writer = (sp == 0) && (tid == 0);

    for (int g = 0; g < SEGLEN / SG2; g++) {
        const int buf = g & 1;
#pragma unroll
        for (int q = 0; q < SG2; q++) {
            sh[buf][q][tid] = pre0[q];
            sh[buf][q][sidx1] = pre1[q];
        }
        if (tid < SG2) {
            const float dtr = predt + dtb;
            const float dtv = (dtr > 20.f) ? dtr : log1pf(expf(dtr));
            sh_dta[buf][tid] = make_float2(dtv, expf(dtv * Aval));
        }
        __syncthreads();

        if (g + 1 < SEGLEN / SG2) {
            const size_t l0 = (size_t)(g + 1) * SG2;
#pragma unroll
            for (int q = 0; q < SG2; q++) {
                pre0[q] = colp0[(l0 + q) * CONVD];
                pre1[q] = colp1[(l0 + q) * CONVD];
            }
            if (tid < SG2) predt = dtb_g[(l0 + tid) * DPROJ];
        }

#pragma unroll
        for (int q = 0; q < SG2; q++) {
            const float2 dta = sh_dta[buf][q];
            const float xv = sh[buf][q][tid];
            const float coef = dta.x * xv;
            unsigned long long coef2, dA2;
            F32X2_BCAST(coef2, coef);
            F32X2_BCAST(dA2, dta.y);

            unsigned long long acc2 = 0ULL;
#pragma unroll
            for (int v = 0; v < 8; v++) {
                const ulonglong2 Bp = *reinterpret_cast<const ulonglong2*>(
                    &sh[buf][q][64 + v * 4]);
                const ulonglong2 Cp = *reinterpret_cast<const ulonglong2*>(
                    &sh[buf][q][96 + v * 4]);
                unsigned long long t0, t1;
                F32X2_MUL(t0, coef2, Bp.x);
                F32X2_MUL(t1, coef2, Bp.y);
                F32X2_FMA(s[2 * v], dA2, t0);
                F32X2_FMA(s[2 * v + 1], dA2, t1);
                if (v == 0) F32X2_MUL(acc2, s[0], Cp.x);
                else        F32X2_FMA3(acc2, s[2 * v], Cp.x);
                F32X2_FMA3(acc2, s[2 * v + 1], Cp.y);
            }
            float alo, ahi;
            F32X2_UNPACK(alo, ahi, acc2);
            float acc = alo + ahi;
            if (sp == 0) acc = fmaf(Dv, xv, acc);
            yb[(size_t)(g * SG2 + q) * DINNER] = acc;

            if (cd_writer) {
                cd_run *= dta.y;
                g_cd[(bh * NSEG + seg) * SEGLEN + g * SG2 + q] = cd_run;
            }
        }
    }

    if (seg < NSEG - 1) {
        float* sst = g_sloc + (((size_t)bh * NSEG + seg) * HEADDIM + tid) * DSTATE
                   + sp * 32;
#pragma unroll
        for (int v = 0; v < 16; v++) {
            float lo, hi;
            F32X2_UNPACK(lo, hi, s[v]);
            sst[2 * v] = lo;
            sst[2 * v + 1] = hi;
        }
    }
}

// =====================================================================
// State chain: S_in(0)=0; S_in(j+1) = D_j * S_in(j) + Sloc_j.
// =====================================================================
__global__ __launch_bounds__(256) void scan_chain()
{
    const int pg = blockIdx.x & 7;
    const int bh = blockIdx.x >> 3;
    const int tid = threadIdx.x;
    const int p = pg * 8 + (tid >> 5);
    const int n4 = (tid & 31) * 4;

    const size_t eoff = ((size_t)p) * DSTATE + n4;
    const size_t segstride = (size_t)HEADDIM * DSTATE;
    const float* sloc = g_sloc + (size_t)bh * NSEG * segstride + eoff;
    float* scar = g_scarry + (size_t)bh * NSEG * segstride + eoff;

    float4 carry = make_float4(0.f, 0.f, 0.f, 0.f);
#pragma unroll
    for (int j = 0; j < NSEG; j++) {
        *reinterpret_cast<float4*>(scar + (size_t)j * segstride) = carry;
        if (j < NSEG - 1) {
            const float D = g_cd[(bh * NSEG + j) * SEGLEN + SEGLEN - 1];
            const float4 sl = *reinterpret_cast<const float4*>(
                sloc + (size_t)j * segstride);
            carry.x = fmaf(D, carry.x, sl.x);
            carry.y = fmaf(D, carry.y, sl.y);
            carry.z = fmaf(D, carry.z, sl.z);
            carry.w = fmaf(D, carry.w, sl.w);
        }
    }
}

// =====================================================================
// Correction for segments 1..7: y_l += cd_l * (C_l . S_in(seg))
// =====================================================================
__global__ __launch_bounds__(256) void scan_correct()
{
    const int sg1 = blockIdx.x % 7;
    const int seg = sg1 + 1;
    const int bh = blockIdx.x / 7;
    const int b = bh >> 5, h = bh & 31;
    const int tid = threadIdx.x;

    __shared__ __align__(16) float Sst[64][132];
    __shared__ __align__(16) float Cl[64][128];
    __shared__ float cd[64];

    const float* sbase = g_scarry
        + ((size_t)bh * NSEG + seg) * HEADDIM * DSTATE;
    for (int i = tid; i < 2048; i += 256) {
        float4 v = *reinterpret_cast<const float4*>(&sbase[i * 4]);
        int r = i >> 5, c = (i & 31) * 4;
        *reinterpret_cast<float4*>(&Sst[r][c]) = v;
    }
    const size_t row0 = (size_t)(b * SEQLEN + seg * SEGLEN);
    for (int i = tid; i < 2048; i += 256) {
        int l = i >> 5, c = (i & 31) * 4;
        float4 v = *reinterpret_cast<const float4*>(
            &g_xbc[(row0 + l) * CONVD + DINNER + DSTATE + c]);
        *reinterpret_cast<float4*>(&Cl[l][c]) = v;
    }
    if (tid < 64) cd[tid] = g_cd[(bh * NSEG + seg) * SEGLEN + tid];
    __syncthreads();

    const int p = tid & 63;
    const int lg = tid >> 6;

    unsigned long long accll[16];
#pragma unroll
    for (int i = 0; i < 16; i++) accll[i] = 0ULL;

    for (int n4 = 0; n4 < 32; n4++) {
        const ulonglong2 sv = *reinterpret_cast<const ulonglong2*>(
            &Sst[p][n4 * 4]);
#pragma unroll
        for (int i = 0; i < 16; i++) {
            const ulonglong2 cv = *reinterpret_cast<const ulonglong2*>(
                &Cl[lg * 16 + i][n4 * 4]);
            F32X2_FMA3(accll[i], cv.x, sv.x);
            F32X2_FMA3(accll[i], cv.y, sv.y);
        }
    }

#pragma unroll
    for (int i = 0; i < 16; i++) {
        const int l = lg * 16 + i;
        float lo, hi;
        F32X2_UNPACK(lo, hi, accll[i]);
        const float corr = (lo + hi) * cd[l];
        float* yp = g_yp[0] + (row0 + l) * DINNER + h * HEADDIM + p;
        *yp += corr;
    }
}

// =====================================================================
// Gated RMSNorm (sums 4 scan partials, float4 loads) -> fp16 hi only
// =====================================================================
__global__ __launch_bounds__(256) void gated_norm_kernel(
    const float* __restrict__ nw)
{
    const int row = blockIdx.x;
    const int tid = threadIdx.x;
    const int c0 = tid * 8;
    __shared__ float red[256];

    const size_t base = (size_t)row * DINNER + c0;
    float4 v0 = make_float4(0.f, 0.f, 0.f, 0.f);
    float4 v1 = v0;
#pragma unroll
    for (int k = 0; k < 4; k++) {
        float4 a = *reinterpret_cast<const float4*>(&g_yp[k][base]);
        float4 c = *reinterpret_cast<const float4*>(&g_yp[k][base + 4]);
        v0.x += a.x; v0.y += a.y; v0.z += a.z; v0.w += a.w;
        v1.x += c.x; v1.y += c.y; v1.z += c.z; v1.w += c.w;
    }
    const float4 z0 = *reinterpret_cast<const float4*>(
        &g_zx[(size_t)row * DPROJ + c0]);
    const float4 z1 = *reinterpret_cast<const float4*>(
        &g_zx[(size_t)row * DPROJ + c0 + 4]);

    float vals[8];
    vals[0] = v0.x * (z0.x / (1.f + expf(-z0.x)));
    vals[1] = v0.y * (z0.y / (1.f + expf(-z0.y)));
    vals[2] = v0.z * (z0.z / (1.f + expf(-z0.z)));
    vals[3] = v0.w * (z0.w / (1.f + expf(-z0.w)));
    vals[4] = v1.x * (z1.x / (1.f + expf(-z1.x)));
    vals[5] = v1.y * (z1.y / (1.f + expf(-z1.y)));
    vals[6] = v1.z * (z1.z / (1.f + expf(-z1.z)));
    vals[7] = v1.w * (z1.w / (1.f + expf(-z1.w)));

    float ss = 0.f;
#pragma unroll
    for (int i = 0; i < 8; i++) ss = fmaf(vals[i], vals[i], ss);

    red[tid] = ss;
    __syncthreads();
#pragma unroll
    for (int stride = 128; stride >= 32; stride >>= 1) {
        if (tid < stride) red[tid] += red[tid + stride];
        __syncthreads();
    }
    if (tid < 32) {
        float v = red[tid];
#pragma unroll
        for (int o = 16; o > 0; o >>= 1)
            v += __shfl_down_sync(0xffffffffu, v, o);
        if (tid == 0) red[0] = v;
    }
    __syncthreads();
    const float scale = rsqrtf(red[0] / (float)DINNER + 1e-5f);

    const float4 w0 = *reinterpret_cast<const float4*>(&nw[c0]);
    const float4 w1 = *reinterpret_cast<const float4*>(&nw[c0 + 4]);
    float o[8];
    o[0] = vals[0] * scale * w0.x;  o[1] = vals[1] * scale * w0.y;
    o[2] = vals[2] * scale * w0.z;  o[3] = vals[3] * scale * w0.w;
    o[4] = vals[4] * scale * w1.x;  o[5] = vals[5] * scale * w1.y;
    o[6] = vals[6] * scale * w1.z;  o[7] = vals[7] * scale * w1.w;

    uint4 hpack;
    hpack.x = pack_h2(o[0], o[1]);  hpack.y = pack_h2(o[2], o[3]);
    hpack.z = pack_h2(o[4], o[5]);  hpack.w = pack_h2(o[6], o[7]);
    *reinterpret_cast<uint4*>(&g_ynh[base]) = hpack;
}

// =====================================================================
// launch
// =====================================================================
extern "C" void kernel_launch(void* const* d_in, const int* in_sizes, int n_in,
                              void* d_out, int out_size)
{
    const float* u       = (const float*)d_in[0];
    const float* W_in    = (const float*)d_in[1];
    const float* conv_w  = (const float*)d_in[2];
    const float* conv_b  = (const float*)d_in[3];
    const float* dt_bias = (const float*)d_in[4];
    const float* A_log   = (const float*)d_in[5];
    const float* D_param = (const float*)d_in[6];
    const float* norm_w  = (const float*)d_in[7];
    const float* W_out   = (const float*)d_in[8];
    float* out = (float*)d_out;

    float* zx;
    cudaGetSymbolAddress((void**)&zx, g_zx);
    __half *uh, *ul, *wih, *ynh, *woh;
    cudaGetSymbolAddress((void**)&uh,  g_uh);
    cudaGetSymbolAddress((void**)&ul,  g_ul);
    cudaGetSymbolAddress((void**)&wih, g_wih);
    cudaGetSymbolAddress((void**)&ynh, g_ynh);
    cudaGetSymbolAddress((void**)&woh, g_woh);

    cudaFuncSetAttribute(gemm_f16_2t,
                         cudaFuncAttributeMaxDynamicSharedMemorySize, GS_SMEM);

    // 0) merged vectorized conversions
    convert_all<<<(CVT_TOT / 4 + 255) / 256, 256>>>(u, W_in, W_out);

    // 1) in_proj: single-term except last n-tile (dt cols) is 2-term
    {
        dim3 grid(NPAD / 256, MROWS / 128, 1);
        gemm_f16_2t<<<grid, 256, GS_SMEM>>>(uh, ul, wih, zx,
                                            MROWS, DPROJ, DMODEL, 0, 2);
    }

    // 2) depthwise conv + silu (4 l per thread)
    {
        int total = (MROWS / 4) * CONVD;
        conv_silu_kernel<<<(total + 255) / 256, 256>>>(conv_w, conv_b);
    }

    // 3a) segmented SSM scan: 2048 blocks of 64 threads
    ssm_scan_seg<<<64 * NSEG * 4, 64>>>(dt_bias, A_log, D_param);

    // 3b) state chain across segments
    scan_chain<<<64 * 8, 256>>>();

    // 3c) state-carry correction for segments 1..7
    scan_correct<<<64 * 7, 256>>>();

    // 4) gated RMSNorm (sums 4 partials, emits fp16 hi only)
    gated_norm_kernel<<<MROWS, 256>>>(norm_w);

    // 5) out_proj (single-term fp16): split-K=4 -- 128 CTAs
    cudaMemsetAsync(out, 0, (size_t)out_size * sizeof(float));
    {
        dim3 grid(DMODEL / 256, MROWS / 128, 4);
        gemm_f16_2t<<<grid, 256, GS_SMEM>>>(ynh, ynh, woh, out,
                                            MROWS, DMODEL, DINNER, 1, 0);
    }
}

// round 17
// speedup vs baseline: 1.1822x; 1.0259x over previous
#include <cuda_runtime.h>
#include <cuda_fp16.h>
#include <math.h>
#include <stdint.h>

// ---------------- problem constants ----------------
#define BATCH   2
#define SEQLEN  512
#define DMODEL  1024
#define DINNER  2048
#define NHEADS  32
#define HEADDIM 64
#define DSTATE  128
#define DCONV   4
#define DPROJ   4384   // 2*DINNER + 2*DSTATE + NHEADS
#define NPAD    4608   // DPROJ padded to multiple of 256
#define CONVD   2304   // DINNER + 2*DSTATE
#define MROWS   (BATCH*SEQLEN)   // 1024
#define DT_OFF  (DINNER + CONVD) // 4352
#define NSEG    8
#define SEGLEN  64               // SEQLEN / NSEG

// ---------------- scratch (static device memory) ----------------
__device__ float g_zx [MROWS * DPROJ];      // in_proj output  (1024 x 4384)
__device__ float g_dt [MROWS * 256];        // dt columns (2-term, compact)
__device__ float g_xbc[MROWS * CONVD];      // conv+silu output
__device__ float g_yp [4][MROWS * DINNER];  // scan partial outputs (4 n-chunks)
__device__ float g_sloc  [64 * NSEG * HEADDIM * DSTATE];  // local seg-final states
__device__ float g_scarry[64 * NSEG * HEADDIM * DSTATE];  // chained start states
__device__ float g_cd[64 * NSEG * SEGLEN];  // per-step cumulative decay

__device__ __half g_uh [MROWS * DMODEL];
__device__ __half g_ul [MROWS * DMODEL];
__device__ __half g_wih[NPAD  * DMODEL];
__device__ __half g_ynh[MROWS * DINNER];
__device__ __half g_woh[DMODEL * DINNER];

// =====================================================================
// helpers
// =====================================================================
__device__ __forceinline__ uint32_t smem_u32(const void* p) {
    uint32_t a;
    asm("{ .reg .u64 t; cvta.to.shared.u64 t, %1; cvt.u32.u64 %0, t; }"
        : "=r"(a) : "l"(p));
    return a;
}

__device__ __forceinline__ void cpa16(uint32_t dst, const void* src) {
    asm volatile("cp.async.cg.shared.global [%0], [%1], 16;"
                 :: "r"(dst), "l"(src) : "memory");
}
#define CP_COMMIT() asm volatile("cp.async.commit_group;" ::: "memory")

__device__ __forceinline__ void ldsm_x4(uint32_t addr, uint32_t& r0, uint32_t& r1,
                                        uint32_t& r2, uint32_t& r3) {
    asm volatile("ldmatrix.sync.aligned.m8n8.x4.shared.b16 {%0,%1,%2,%3}, [%4];"
                 : "=r"(r0), "=r"(r1), "=r"(r2), "=r"(r3) : "r"(addr));
}

__device__ __forceinline__ void mma_f16(float* c, const uint32_t* a,
                                        uint32_t b0, uint32_t b1) {
    asm volatile(
        "mma.sync.aligned.m16n8k16.row.col.f32.f16.f16.f32 "
        "{%0,%1,%2,%3}, {%4,%5,%6,%7}, {%8,%9}, {%0,%1,%2,%3};"
        : "+f"(c[0]), "+f"(c[1]), "+f"(c[2]), "+f"(c[3])
        : "r"(a[0]), "r"(a[1]), "r"(a[2]), "r"(a[3]), "r"(b0), "r"(b1));
}

__device__ __forceinline__ uint32_t pack_h2(float a, float b) {
    __half2 h = __floats2half2_rn(a, b);
    return *reinterpret_cast<uint32_t*>(&h);
}

#define F32X2_MUL(d, a, b) \
    asm("mul.rn.f32x2 %0, %1, %2;" : "=l"(d) : "l"(a), "l"(b))
#define F32X2_FMA(d, a, b) \
    asm("fma.rn.f32x2 %0, %0, %1, %2;" : "+l"(d) : "l"(a), "l"(b))
#define F32X2_FMA3(d, a, b) \
    asm("fma.rn.f32x2 %0, %1, %2, %0;" : "+l"(d) : "l"(a), "l"(b))
#define F32X2_BCAST(d, f) \
    asm("mov.b64 %0, {%1, %1};" : "=l"(d) : "f"(f))
#define F32X2_UNPACK(lo, hi, v) \
    asm("mov.b64 {%0, %1}, %2;" : "=f"(lo), "=f"(hi) : "l"(v))

// =====================================================================
// merged, vectorized fp32 -> fp16 conversions (u hi/lo, W_in hi, W_out hi)
// =====================================================================
#define CVT_N0 (MROWS * DMODEL)
#define CVT_N1 (NPAD * DMODEL)
#define CVT_N2 (DMODEL * DINNER)
#define CVT_TOT (CVT_N0 + CVT_N1 + CVT_N2)

__global__ __launch_bounds__(256) void convert_all(
    const float* __restrict__ u, const float* __restrict__ W_in,
    const float* __restrict__ W_out)
{
    int i = (blockIdx.x * 256 + threadIdx.x) * 4;
    if (i < CVT_N0) {
        float4 v = *reinterpret_cast<const float4*>(&u[i]);
        float hx = __half2float(__float2half_rn(v.x));
        float hy = __half2float(__float2half_rn(v.y));
        float hz = __half2float(__float2half_rn(v.z));
        float hw = __half2float(__float2half_rn(v.w));
        *reinterpret_cast<uint2*>(&g_uh[i]) =
            make_uint2(pack_h2(v.x, v.y), pack_h2(v.z, v.w));
        *reinterpret_cast<uint2*>(&g_ul[i]) =
            make_uint2(pack_h2(v.x - hx, v.y - hy), pack_h2(v.z - hz, v.w - hw));
    } else if (i < CVT_N0 + CVT_N1) {
        int j = i - CVT_N0;
        float4 v = make_float4(0.f, 0.f, 0.f, 0.f);
        if (j < DPROJ * DMODEL)
            v = *reinterpret_cast<const float4*>(&W_in[j]);
        *reinterpret_cast<uint2*>(&g_wih[j]) =
            make_uint2(pack_h2(v.x, v.y), pack_h2(v.z, v.w));
    } else if (i < CVT_TOT) {
        int j = i - CVT_N0 - CVT_N1;
        float4 v = *reinterpret_cast<const float4*>(&W_out[j]);
        *reinterpret_cast<uint2*>(&g_woh[j]) =
            make_uint2(pack_h2(v.x, v.y), pack_h2(v.z, v.w));
    }
}

// =====================================================================
// fp16 split GEMM (NT): C[m,n] = sum_k A[m,k]*B[n,k]
// two_term=0: Ah*Bh;  two_term=1: Ah*Bh + Al*Bh.
// CTA 128x256, 8 warps, warp tile 64x64, BK=32, 3-stage cp.async.
// =====================================================================
#define GS_ROWB 80
#define GS_STGB (512*GS_ROWB)
#define GS_SMEM (3*GS_STGB)
#define GS_AL_OFF (128*GS_ROWB)
#define GS_BH_OFF (256*GS_ROWB)

__global__ __launch_bounds__(256) void gemm_f16_2t(
    const __half* __restrict__ Ah, const __half* __restrict__ Al,
    const __half* __restrict__ Bh,
    float* __restrict__ C, int M, int N, int K, int accum, int two_term)
{
    extern __shared__ char smem[];
    const uint32_t sbase = smem_u32(smem);
    const int tid = threadIdx.x;
    const int lane = tid & 31;
    const int warp = tid >> 5;
    const int wm = (warp >> 2) * 64;
    const int wn = (warp & 3) * 64;

    const int m0 = blockIdx.y * 128;
    const int n0 = blockIdx.x * 256;
    const int kslice = K / gridDim.z;
    const int kbeg = blockIdx.z * kslice;
    const int T = kslice / 32;

    float acc[4][8][4];
#pragma unroll
    for (int i = 0; i < 4; i++)
#pragma unroll
        for (int j = 0; j < 8; j++)
#pragma unroll
            for (int q = 0; q < 4; q++) acc[i][j][q] = 0.f;

    const __half* ptr0 = (tid < 128)
        ? Ah + (size_t)(m0 + tid) * K + kbeg
        : Al + (size_t)(m0 + tid - 128) * K + kbeg;
    const __half* ptr1 = Bh + (size_t)(n0 + tid) * K + kbeg;
    const uint32_t srow0 = sbase + tid * GS_ROWB;
    const uint32_t srow1 = sbase + (tid + 256) * GS_ROWB;
    const bool fill0 = two_term || (tid < 128);

#define FILL_STAGE(STG, KOFF)                                                  \
    {                                                                          \
        uint32_t s0 = srow0 + (STG) * GS_STGB;                                 \
        uint32_t s1 = srow1 + (STG) * GS_STGB;                                 \
        _Pragma("unroll")                                                      \
        for (int sg = 0; sg < 4; sg++) {                                       \
            if (fill0) cpa16(s0 + sg * 16, ptr0 + (KOFF) + sg * 8);            \
            cpa16(s1 + sg * 16, ptr1 + (KOFF) + sg * 8);                       \
        }                                                                      \
    }

    const uint32_t a_off = (uint32_t)((wm + (lane & 15)) * GS_ROWB + (lane >> 4) * 16);
    const uint32_t b_row = (uint32_t)(wn + ((lane >> 4) << 3) + (lane & 7));
    const uint32_t b_off = GS_BH_OFF + b_row * GS_ROWB + (((lane >> 3) & 1) << 4);

    FILL_STAGE(0, 0);
    CP_COMMIT();
    FILL_STAGE(1, 32);
    CP_COMMIT();

    for (int t = 0; t < T; t++) {
        asm volatile("cp.async.wait_group 1;" ::: "memory");
        __syncthreads();
        if (t + 2 < T) {
            int stg = (t + 2) % 3;
            FILL_STAGE(stg, (t + 2) * 32);
            CP_COMMIT();
        }

        const uint32_t sb = sbase + (t % 3) * GS_STGB;
#pragma unroll
        for (int ks = 0; ks < 2; ks++) {
            const uint32_t kb = ks * 32;
            uint32_t ah[4][4], al[4][4], bh[4][4];
#pragma unroll
            for (int mi = 0; mi < 4; mi++) {
                uint32_t ad = sb + a_off + mi * 16 * GS_ROWB + kb;
                ldsm_x4(ad, ah[mi][0], ah[mi][1], ah[mi][2], ah[mi][3]);
                if (two_term)
                    ldsm_x4(ad + GS_AL_OFF, al[mi][0], al[mi][1], al[mi][2], al[mi][3]);
            }
#pragma unroll
            for (int bi = 0; bi < 4; bi++) {
                uint32_t bd = sb + b_off + bi * 16 * GS_ROWB + kb;
                ldsm_x4(bd, bh[bi][0], bh[bi][1], bh[bi][2], bh[bi][3]);
            }
#pragma unroll
            for (int mi = 0; mi < 4; mi++)
#pragma unroll
                for (int ni = 0; ni < 8; ni++)
                    mma_f16(acc[mi][ni], ah[mi],
                            bh[ni >> 1][(ni & 1) * 2], bh[ni >> 1][(ni & 1) * 2 + 1]);
            if (two_term) {
#pragma unroll
                for (int mi = 0; mi < 4; mi++)
#pragma unroll
                    for (int ni = 0; ni < 8; ni++)
                        mma_f16(acc[mi][ni], al[mi],
                                bh[ni >> 1][(ni & 1) * 2], bh[ni >> 1][(ni & 1) * 2 + 1]);
            }
        }
    }

#pragma unroll
    for (int mi = 0; mi < 4; mi++) {
        const int r0 = m0 + wm + mi * 16 + (lane >> 2);
#pragma unroll
        for (int ni = 0; ni < 8; ni++) {
            const int c = n0 + wn + ni * 8 + (lane & 3) * 2;
            if (c < N) {
                float* p0 = C + (size_t)r0 * N + c;
                float* p1 = C + (size_t)(r0 + 8) * N + c;
                if (accum) {
                    atomicAdd(&p0[0], acc[mi][ni][0]);
                    atomicAdd(&p0[1], acc[mi][ni][1]);
                    atomicAdd(&p1[0], acc[mi][ni][2]);
                    atomicAdd(&p1[1], acc[mi][ni][3]);
                } else {
                    p0[0] = acc[mi][ni][0];
                    p0[1] = acc[mi][ni][1];
                    p1[0] = acc[mi][ni][2];
                    p1[1] = acc[mi][ni][3];
                }
            }
        }
    }
#undef FILL_STAGE
}

// =====================================================================
// Depthwise causal conv (k=4) + bias + SiLU.
// Thread computes 4 consecutive l for one channel: 7 loads / 4 outputs.
// =====================================================================
__global__ __launch_bounds__(256) void conv_silu_kernel(
    const float* __restrict__ cw, const float* __restrict__ cb)
{
    int idx = blockIdx.x * blockDim.x + threadIdx.x;
    if (idx >= (MROWS / 4) * CONVD) return;
    const int c = idx % CONVD;
    const int lq = idx / CONVD;
    const int l0 = (lq & (SEQLEN / 4 - 1)) * 4;
    const int b = lq / (SEQLEN / 4);

    const float w0 = cw[c * DCONV + 0];
    const float w1 = cw[c * DCONV + 1];
    const float w2 = cw[c * DCONV + 2];
    const float w3 = cw[c * DCONV + 3];
    const float bias = cb[c];

    const float* zb = g_zx + (size_t)(b * SEQLEN) * DPROJ + DINNER + c;
    float v[7];
#pragma unroll
    for (int j = 0; j < 7; j++) {
        const int l = l0 - 3 + j;
        v[j] = (l >= 0) ? zb[(size_t)l * DPROJ] : 0.f;
    }

    float* ob = g_xbc + (size_t)(b * SEQLEN + l0) * CONVD + c;
#pragma unroll
    for (int q = 0; q < 4; q++) {
        float a = bias;
        a = fmaf(w0, v[q], a);
        a = fmaf(w1, v[q + 1], a);
        a = fmaf(w2, v[q + 2], a);
        a = fmaf(w3, v[q + 3], a);
        ob[(size_t)q * CONVD] = a / (1.f + expf(-a));
    }
}

// =====================================================================
// SSM scan, 8 segments x 64 steps, 4-way state split.
// dt read from compact g_dt buffer (stride 256).
// =====================================================================
#define SG2 4
__global__ __launch_bounds__(64) void ssm_scan_seg(
    const float* __restrict__ dt_bias, const float* __restrict__ A_log,
    const float* __restrict__ Dp)
{
    const int bid = blockIdx.x;
    const int sp  = bid & 3;
    const int seg = (bid >> 2) & 7;
    const int bh  = bid >> 5;
    const int b = bh >> 5, h = bh & 31;
    const int tid = threadIdx.x;

    __shared__ __align__(16) float sh[2][SG2][128];
    __shared__ float2 sh_dta[2][SG2];

    unsigned long long s[16];
#pragma unroll
    for (int i = 0; i < 16; i++) s[i] = 0ULL;

    const float Aval = -expf(A_log[h]);
    const float dtb  = dt_bias[h];
    const float Dv   = Dp[h];

    const size_t row0 = (size_t)(b * SEQLEN + seg * SEGLEN);
    const float* xb = g_xbc + row0 * CONVD;
    const float* dtb_g = g_dt + row0 * 256 + h;

    const float* colp0 = xb + h * HEADDIM + tid;
    const float* colp1 = (tid < 32)
        ? xb + DINNER + sp * 32 + tid
        : xb + DINNER + DSTATE + sp * 32 + (tid - 32);
    const int sidx1 = 64 + tid;

    float pre0[SG2], pre1[SG2];
#pragma unroll
    for (int q = 0; q < SG2; q++) {
        pre0[q] = colp0[(size_t)q * CONVD];
        pre1[q] = colp1[(size_t)q * CONVD];
    }
    float predt = (tid < SG2) ? dtb_g[(size_t)tid * 256] : 0.f;

    float* yb = g_yp[sp] + row0 * DINNER + h * HEADDIM + tid;
    float cd_run = 1.f;
    const bool cd_writer = (sp == 0) && (tid == 0);

    for (int g = 0; g < SEGLEN / SG2; g++) {
        const int buf = g & 1;
#pragma unroll
        for (int q = 0; q < SG2; q++) {
            sh[buf][q][tid] = pre0[q];
            sh[buf][q][sidx1] = pre1[q];
        }
        if (tid < SG2) {
            const float dtr = predt + dtb;
            const float dtv = (dtr > 20.f) ? dtr : log1pf(expf(dtr));
            sh_dta[buf][tid] = make_float2(dtv, expf(dtv * Aval));
        }
        __syncthreads();

        if (g + 1 < SEGLEN / SG2) {
            const size_t l0 = (size_t)(g + 1) * SG2;
#pragma unroll
            for (int q = 0; q < SG2; q++) {
                pre0[q] = colp0[(l0 + q) * CONVD];
                pre1[q] = colp1[(l0 + q) * CONVD];
            }
            if (tid < SG2) predt = dtb_g[(l0 + tid) * 256];
        }

#pragma unroll
        for (int q = 0; q < SG2; q++) {
            const float2 dta = sh_dta[buf][q];
            const float xv = sh[buf][q][tid];
            const float coef = dta.x * xv;
            unsigned long long coef2, dA2;
            F32X2_BCAST(coef2, coef);
            F32X2_BCAST(dA2, dta.y);

            unsigned long long acc2 = 0ULL;
#pragma unroll
            for (int v = 0; v < 8; v++) {
                const ulonglong2 Bp = *reinterpret_cast<const ulonglong2*>(
                    &sh[buf][q][64 + v * 4]);
                const ulonglong2 Cp = *reinterpret_cast<const ulonglong2*>(
                    &sh[buf][q][96 + v * 4]);
                unsigned long long t0, t1;
                F32X2_MUL(t0, coef2, Bp.x);
                F32X2_MUL(t1, coef2, Bp.y);
                F32X2_FMA(s[2 * v], dA2, t0);
                F32X2_FMA(s[2 * v + 1], dA2, t1);
                if (v == 0) F32X2_MUL(acc2, s[0], Cp.x);
                else        F32X2_FMA3(acc2, s[2 * v], Cp.x);
                F32X2_FMA3(acc2, s[2 * v + 1], Cp.y);
            }
            float alo, ahi;
            F32X2_UNPACK(alo, ahi, acc2);
            float acc = alo + ahi;
            if (sp == 0) acc = fmaf(Dv, xv, acc);
            yb[(size_t)(g * SG2 + q) * DINNER] = acc;

            if (cd_writer) {
                cd_run *= dta.y;
                g_cd[(bh * NSEG + seg) * SEGLEN + g * SG2 + q] = cd_run;
            }
        }
    }

    if (seg < NSEG - 1) {
        float* sst = g_sloc + (((size_t)bh * NSEG + seg) * HEADDIM + tid) * DSTATE
                   + sp * 32;
#pragma unroll
        for (int v = 0; v < 16; v++) {
            float lo, hi;
            F32X2_UNPACK(lo, hi, s[v]);
            sst[2 * v] = lo;
            sst[2 * v + 1] = hi;
        }
    }
}

// =====================================================================
// State chain: S_in(0)=0; S_in(j+1) = D_j * S_in(j) + Sloc_j.
// =====================================================================
__global__ __launch_bounds__(256) void scan_chain()
{
    const int pg = blockIdx.x & 7;
    const int bh = blockIdx.x >> 3;
    const int tid = threadIdx.x;
    const int p = pg * 8 + (tid >> 5);
    const int n4 = (tid & 31) * 4;

    const size_t eoff = ((size_t)p) * DSTATE + n4;
    const size_t segstride = (size_t)HEADDIM * DSTATE;
    const float* sloc = g_sloc + (size_t)bh * NSEG * segstride + eoff;
    float* scar = g_scarry + (size_t)bh * NSEG * segstride + eoff;

    float4 carry = make_float4(0.f, 0.f, 0.f, 0.f);
#pragma unroll
    for (int j = 0; j < NSEG; j++) {
        *reinterpret_cast<float4*>(scar + (size_t)j * segstride) = carry;
        if (j < NSEG - 1) {
            const float D = g_cd[(bh * NSEG + j) * SEGLEN + SEGLEN - 1];
            const float4 sl = *reinterpret_cast<const float4*>(
                sloc + (size_t)j * segstride);
            carry.x = fmaf(D, carry.x, sl.x);
            carry.y = fmaf(D, carry.y, sl.y);
            carry.z = fmaf(D, carry.z, sl.z);
            carry.w = fmaf(D, carry.w, sl.w);
        }
    }
}

// =====================================================================
// Correction for segments 1..7: y_l += cd_l * (C_l . S_in(seg))
// =====================================================================
__global__ __launch_bounds__(256) void scan_correct()
{
    const int sg1 = blockIdx.x % 7;
    const int seg = sg1 + 1;
    const int bh = blockIdx.x / 7;
    const int b = bh >> 5, h = bh & 31;
    const int tid = threadIdx.x;

    __shared__ __align__(16) float Sst[64][132];
    __shared__ __align__(16) float Cl[64][128];
    __shared__ float cd[64];

    const float* sbase = g_scarry
        + ((size_t)bh * NSEG + seg) * HEADDIM * DSTATE;
    for (int i = tid; i < 2048; i += 256) {
        float4 v = *reinterpret_cast<const float4*>(&sbase[i * 4]);
        int r = i >> 5, c = (i & 31) * 4;
        *reinterpret_cast<float4*>(&Sst[r][c]) = v;
    }
    const size_t row0 = (size_t)(b * SEQLEN + seg * SEGLEN);
    for (int i = tid; i < 2048; i += 256) {
        int l = i >> 5, c = (i & 31) * 4;
        float4 v = *reinterpret_cast<const float4*>(
            &g_xbc[(row0 + l) * CONVD + DINNER + DSTATE + c]);
        *reinterpret_cast<float4*>(&Cl[l][c]) = v;
    }
    if (tid < 64) cd[tid] = g_cd[(bh * NSEG + seg) * SEGLEN + tid];
    __syncthreads();

    const int p = tid & 63;
    const int lg = tid >> 6;

    unsigned long long accll[16];
#pragma unroll
    for (int i = 0; i < 16; i++) accll[i] = 0ULL;

    for (int n4 = 0; n4 < 32; n4++) {
        const ulonglong2 sv = *reinterpret_cast<const ulonglong2*>(
            &Sst[p][n4 * 4]);
#pragma unroll
        for (int i = 0; i < 16; i++) {
            const ulonglong2 cv = *reinterpret_cast<const ulonglong2*>(
                &Cl[lg * 16 + i][n4 * 4]);
            F32X2_FMA3(accll[i], cv.x, sv.x);
            F32X2_FMA3(accll[i], cv.y, sv.y);
        }
    }

#pragma unroll
    for (int i = 0; i < 16; i++) {
        const int l = lg * 16 + i;
        float lo, hi;
        F32X2_UNPACK(lo, hi, accll[i]);
        const float corr = (lo + hi) * cd[l];
        float* yp = g_yp[0] + (row0 + l) * DINNER + h * HEADDIM + p;
        *yp += corr;
    }
}

// =====================================================================
// Gated RMSNorm (sums 4 scan partials, float4 loads) -> fp16 hi only
// =====================================================================
__global__ __launch_bounds__(256) void gated_norm_kernel(
    const float* __restrict__ nw)
{
    const int row = blockIdx.x;
    const int tid = threadIdx.x;
    const int c0 = tid * 8;
    __shared__ float red[256];

    const size_t base = (size_t)row * DINNER + c0;
    float4 v0 = make_float4(0.f, 0.f, 0.f, 0.f);
    float4 v1 = v0;
#pragma unroll
    for (int k = 0; k < 4; k++) {
        float4 a = *reinterpret_cast<const float4*>(&g_yp[k][base]);
        float4 c = *reinterpret_cast<const float4*>(&g_yp[k][base + 4]);
        v0.x += a.x; v0.y += a.y; v0.z += a.z; v0.w += a.w;
        v1.x += c.x; v1.y += c.y; v1.z += c.z; v1.w += c.w;
    }
    const float4 z0 = *reinterpret_cast<const float4*>(
        &g_zx[(size_t)row * DPROJ + c0]);
    const float4 z1 = *reinterpret_cast<const float4*>(
        &g_zx[(size_t)row * DPROJ + c0 + 4]);

    float vals[8];
    vals[0] = v0.x * (z0.x / (1.f + expf(-z0.x)));
    vals[1] = v0.y * (z0.y / (1.f + expf(-z0.y)));
    vals[2] = v0.z * (z0.z / (1.f + expf(-z0.z)));
    vals[3] = v0.w * (z0.w / (1.f + expf(-z0.w)));
    vals[4] = v1.x * (z1.x / (1.f + expf(-z1.x)));
    vals[5] = v1.y * (z1.y / (1.f + expf(-z1.y)));
    vals[6] = v1.z * (z1.z / (1.f + expf(-z1.z)));
    vals[7] = v1.w * (z1.w / (1.f + expf(-z1.w)));

    float ss = 0.f;
#pragma unroll
    for (int i = 0; i < 8; i++) ss = fmaf(vals[i], vals[i], ss);

    red[tid] = ss;
    __syncthreads();
#pragma unroll
    for (int stride = 128; stride >= 32; stride >>= 1) {
        if (tid < stride) red[tid] += red[tid + stride];
        __syncthreads();
    }
    if (tid < 32) {
        float v = red[tid];
#pragma unroll
        for (int o = 16; o > 0; o >>= 1)
            v += __shfl_down_sync(0xffffffffu, v, o);
        if (tid == 0) red[0] = v;
    }
    __syncthreads();
    const float scale = rsqrtf(red[0] / (float)DINNER + 1e-5f);

    const float4 w0 = *reinterpret_cast<const float4*>(&nw[c0]);
    const float4 w1 = *reinterpret_cast<const float4*>(&nw[c0 + 4]);
    float o[8];
    o[0] = vals[0] * scale * w0.x;  o[1] = vals[1] * scale * w0.y;
    o[2] = vals[2] * scale * w0.z;  o[3] = vals[3] * scale * w0.w;
    o[4] = vals[4] * scale * w1.x;  o[5] = vals[5] * scale * w1.y;
    o[6] = vals[6] * scale * w1.z;  o[7] = vals[7] * scale * w1.w;

    uint4 hpack;
    hpack.x = pack_h2(o[0], o[1]);  hpack.y = pack_h2(o[2], o[3]);
    hpack.z = pack_h2(o[4], o[5]);  hpack.w = pack_h2(o[6], o[7]);
    *reinterpret_cast<uint4*>(&g_ynh[base]) = hpack;
}

// =====================================================================
// launch
// =====================================================================
extern "C" void kernel_launch(void* const* d_in, const int* in_sizes, int n_in,
                              void* d_out, int out_size)
{
    const float* u       = (const float*)d_in[0];
    const float* W_in    = (const float*)d_in[1];
    const float* conv_w  = (const float*)d_in[2];
    const float* conv_b  = (const float*)d_in[3];
    const float* dt_bias = (const float*)d_in[4];
    const float* A_log   = (const float*)d_in[5];
    const float* D_param = (const float*)d_in[6];
    const float* norm_w  = (const float*)d_in[7];
    const float* W_out   = (const float*)d_in[8];
    float* out = (float*)d_out;

    float *zx, *dtb;
    cudaGetSymbolAddress((void**)&zx, g_zx);
    cudaGetSymbolAddress((void**)&dtb, g_dt);
    __half *uh, *ul, *wih, *ynh, *woh;
    cudaGetSymbolAddress((void**)&uh,  g_uh);
    cudaGetSymbolAddress((void**)&ul,  g_ul);
    cudaGetSymbolAddress((void**)&wih, g_wih);
    cudaGetSymbolAddress((void**)&ynh, g_ynh);
    cudaGetSymbolAddress((void**)&woh, g_woh);

    cudaFuncSetAttribute(gemm_f16_2t,
                         cudaFuncAttributeMaxDynamicSharedMemorySize, GS_SMEM);

    // 0) merged vectorized conversions + zero dt buffer
    convert_all<<<(CVT_TOT / 4 + 255) / 256, 256>>>(u, W_in, W_out);
    cudaMemsetAsync(dtb, 0, (size_t)MROWS * 256 * sizeof(float));

    // 1a) in_proj main: all single-term, balanced -- 144 CTAs
    {
        dim3 grid(NPAD / 256, MROWS / 128, 1);
        gemm_f16_2t<<<grid, 256, GS_SMEM>>>(uh, ul, wih, zx,
                                            MROWS, DPROJ, DMODEL, 0, 0);
    }

    // 1b) dt columns (rows 4352..4607 of W_in): 2-term, split-K=8 -> g_dt
    {
        dim3 grid(1, MROWS / 128, 8);
        gemm_f16_2t<<<grid, 256, GS_SMEM>>>(uh, ul,
                                            wih + (size_t)DT_OFF * DMODEL, dtb,
                                            MROWS, 256, DMODEL, 1, 1);
    }

    // 2) depthwise conv + silu (4 l per thread)
    {
        int total = (MROWS / 4) * CONVD;
        conv_silu_kernel<<<(total + 255) / 256, 256>>>(conv_w, conv_b);
    }

    // 3a) segmented SSM scan: 2048 blocks of 64 threads
    ssm_scan_seg<<<64 * NSEG * 4, 64>>>(dt_bias, A_log, D_param);

    // 3b) state chain across segments
    scan_chain<<<64 * 8, 256>>>();

    // 3c) state-carry correction for segments 1..7
    scan_correct<<<64 * 7, 256>>>();

    // 4) gated RMSNorm (sums 4 partials, emits fp16 hi only)
    gated_norm_kernel<<<MROWS, 256>>>(norm_w);

    // 5) out_proj (single-term fp16): split-K=4 -- 128 CTAs
    cudaMemsetAsync(out, 0, (size_t)out_size * sizeof(float));
    {
        dim3 grid(DMODEL / 256, MROWS / 128, 4);
        gemm_f16_2t<<<grid, 256, GS_SMEM>>>(ynh, ynh, woh, out,
                                            MROWS, DMODEL, DINNER, 1, 0);
    }
}